// round 6
// baseline (speedup 1.0000x reference)
#include <cuda_runtime.h>
#include <cuda_bf16.h>
#include <cstdint>

#define NN 8192
#define KSPLIT 8
#define KCH (NN / KSPLIT)          // 1024
#define NTILES (KCH / 32)          // 32 k-tiles of BK=32

// ---------------------------------------------------------------------------
// Scratch (no cudaMalloc allowed)
// ---------------------------------------------------------------------------
__device__ __nv_bfloat16 gt_hi_dev[64 * NN];      // G^T hi  [D][NN]
__device__ __nv_bfloat16 gt_lo_dev[64 * NN];      // G^T lo
__device__ float part_buf_dev[KSPLIT * NN * 64];  // split-K partials (16 MB)

// ---------------------------------------------------------------------------
// PTX helpers (plain sm_103-legal: mma.sync / ldmatrix / cp.async only)
// ---------------------------------------------------------------------------
__device__ __forceinline__ uint32_t smem_u32(const void* p) {
    uint32_t a;
    asm("{ .reg .u64 t; cvta.to.shared.u64 t, %1; cvt.u32.u64 %0, t; }"
        : "=r"(a) : "l"(p));
    return a;
}
__device__ __forceinline__ void cp16(uint32_t dst, const void* src) {
    asm volatile("cp.async.cg.shared.global [%0], [%1], 16;\n"
                 :: "r"(dst), "l"(src));
}
#define CP_COMMIT() asm volatile("cp.async.commit_group;" ::: "memory")
#define CP_WAIT0()  asm volatile("cp.async.wait_group 0;" ::: "memory")
#define CP_WAIT1()  asm volatile("cp.async.wait_group 1;" ::: "memory")

__device__ __forceinline__ void ldm4(uint32_t* a, uint32_t addr) {
    asm volatile("ldmatrix.sync.aligned.m8n8.x4.shared.b16 {%0,%1,%2,%3}, [%4];"
                 : "=r"(a[0]), "=r"(a[1]), "=r"(a[2]), "=r"(a[3]) : "r"(addr));
}
__device__ __forceinline__ void mma_bf16(float* c, const uint32_t* a,
                                         uint32_t b0, uint32_t b1) {
    asm volatile(
        "mma.sync.aligned.m16n8k16.row.col.f32.bf16.bf16.f32 "
        "{%0,%1,%2,%3},{%4,%5,%6,%7},{%8,%9},{%0,%1,%2,%3};"
        : "+f"(c[0]), "+f"(c[1]), "+f"(c[2]), "+f"(c[3])
        : "r"(a[0]), "r"(a[1]), "r"(a[2]), "r"(a[3]), "r"(b0), "r"(b1));
}
// pack two fp32 -> bf16x2 (x in low half)
__device__ __forceinline__ uint32_t pack_bf2(float lo, float hi) {
    uint32_t r;
    asm("cvt.rn.bf16x2.f32 %0, %1, %2;" : "=r"(r) : "f"(hi), "f"(lo));
    return r;
}

// ---------------------------------------------------------------------------
// Big GEMM: part[ks] = A[:, kchunk] (fp32, split in-kernel) @ G[kchunk, :]
//   BM=128, BK=32, 128 threads = 4 warps; warp tile 32 x D (full width).
//   A: fused LDG fp32 -> cvt bf16 hi/lo -> STS (2 stages, 80B row stride).
//   G: cp.async bf16 hi/lo (3 stages, prefetch distance 2).
//   One __syncthreads per k-tile.
// ---------------------------------------------------------------------------
template<int D>
__global__ void __launch_bounds__(128, 3)
big_mma(const float* __restrict__ A) {
    constexpr int NJ   = D / 8;             // n-tiles of 8 per warp (full D)
    constexpr int GSZ  = D * 80;            // one G plane (hi or lo)
    constexpr int APL  = 128 * 80;          // one A plane = 10240 B
    constexpr int AREA = 4 * APL;           // 2 stages x hi/lo
    constexpr int GPASS = (D * 4) / 128;    // cp16 per plane per thread

    extern __shared__ char smem[];
    const uint32_t sb = smem_u32(smem);
    const int tid  = threadIdx.x;
    const int wid  = tid >> 5;
    const int lane = tid & 31;
    const size_t row0 = (size_t)blockIdx.x * 128;
    const size_t k0   = (size_t)blockIdx.y * KCH;

    // A loader geometry: 16 rows/pass x 8 passes, 1 float4 per row per thread
    const int ar = tid >> 3;                // 0..15
    const int ac = (tid & 7) * 4;           // fp32 col within BK

    // fused load+convert+store of A tile kt into stage s
    auto ldA_stA = [&](int s, int kt) {
        const float* p = A + (row0 + ar) * NN + k0 + (size_t)kt * 32 + ac;
        const uint32_t bo = (uint32_t)(s * 2 * APL + ar * 80 + (tid & 7) * 8);
        #pragma unroll
        for (int i = 0; i < 8; ++i) {
            const float4 v = *(const float4*)(p + (size_t)16 * i * NN);
            uint32_t h01 = pack_bf2(v.x, v.y);
            uint32_t h23 = pack_bf2(v.z, v.w);
            float l0 = v.x - __uint_as_float(h01 << 16);
            float l1 = v.y - __uint_as_float(h01 & 0xFFFF0000u);
            float l2 = v.z - __uint_as_float(h23 << 16);
            float l3 = v.w - __uint_as_float(h23 & 0xFFFF0000u);
            uint32_t lo01 = pack_bf2(l0, l1);
            uint32_t lo23 = pack_bf2(l2, l3);
            const uint32_t off = bo + (uint32_t)(i * 16 * 80);
            *(uint2*)(smem + off)       = make_uint2(h01, h23);
            *(uint2*)(smem + off + APL) = make_uint2(lo01, lo23);
        }
    };
    auto ldG = [&](int g, int kt) {
        #pragma unroll
        for (int p = 0; p < GPASS; ++p) {
            const int c  = p * 128 + tid;
            const int gr = c >> 2;
            const int gs = (c & 3) * 8;
            const uint32_t dst = sb + AREA + (uint32_t)(g * 2 * GSZ + gr * 80 + gs * 2);
            const size_t   go  = (size_t)gr * NN + k0 + (size_t)kt * 32 + gs;
            cp16(dst,       gt_hi_dev + go);
            cp16(dst + GSZ, gt_lo_dev + go);
        }
    };

    float acc[2][NJ][4];
    #pragma unroll
    for (int mb = 0; mb < 2; ++mb)
        #pragma unroll
        for (int j = 0; j < NJ; ++j)
            #pragma unroll
            for (int q = 0; q < 4; ++q) acc[mb][j][q] = 0.0f;

    // prologue: G two tiles ahead (async), A tile 0 into stage 0
    ldG(0, 0); CP_COMMIT();
    ldG(1, 1); CP_COMMIT();
    ldA_stA(0, 0);

    // ldmatrix lane addressing (conflict-free with 80B row stride)
    const uint32_t a_lane = (uint32_t)((lane & 15) * 80 + (lane >> 4) * 16);
    const uint32_t g_lane = (uint32_t)((lane & 7) * 80 + (lane >> 3) * 16);

    for (int kt = 0; kt < NTILES; ++kt) {
        if (kt == NTILES - 1) CP_WAIT0(); else CP_WAIT1();
        __syncthreads();                    // G(kt) + everyone's A(kt) visible

        if (kt + 2 < NTILES) { ldG((kt + 2) % 3, kt + 2); CP_COMMIT(); }
        if (kt + 1 < NTILES) ldA_stA((kt + 1) & 1, kt + 1);  // stage sa^1 free

        const int sa = kt & 1;
        const int sg = kt % 3;

        // A fragments: 2 m16 blocks x 2 kk x hi/lo  (warp owns rows wid*32..+31)
        const uint32_t ab = sb + (uint32_t)(sa * 2 * APL + wid * 32 * 80) + a_lane;
        uint32_t Ah[2][2][4], Al[2][2][4];   // [mb][kk][reg]
        #pragma unroll
        for (int mb = 0; mb < 2; ++mb)
            #pragma unroll
            for (int kk = 0; kk < 2; ++kk) {
                ldm4(Ah[mb][kk], ab + mb * 16 * 80 + kk * 32);
                ldm4(Al[mb][kk], ab + mb * 16 * 80 + kk * 32 + APL);
            }

        const uint32_t gb = sb + AREA + (uint32_t)(sg * 2 * GSZ) + g_lane;
        #pragma unroll
        for (int j = 0; j < NJ; ++j) {
            uint32_t bh[4], bl[4];           // x4 covers kk0 (b0,b1) + kk1 (b0,b1)
            ldm4(bh, gb + j * 8 * 80);
            ldm4(bl, gb + j * 8 * 80 + GSZ);
            #pragma unroll
            for (int mb = 0; mb < 2; ++mb) {
                float* c = acc[mb][j];
                mma_bf16(c, Ah[mb][0], bh[0], bh[1]);
                mma_bf16(c, Ah[mb][1], bh[2], bh[3]);
                mma_bf16(c, Ah[mb][0], bl[0], bl[1]);
                mma_bf16(c, Ah[mb][1], bl[2], bl[3]);
                mma_bf16(c, Al[mb][0], bh[0], bh[1]);
                mma_bf16(c, Al[mb][1], bh[2], bh[3]);
            }
        }
    }

    // epilogue: warp rows wid*32 + mb*16 + lane/4 + {0,8}; cols j*8 + 2*(lane&3)
    float* P = part_buf_dev + ((size_t)blockIdx.y * NN + row0 + wid * 32) * D;
    const int r0 = lane >> 2;
    const int c0 = (lane & 3) * 2;
    #pragma unroll
    for (int mb = 0; mb < 2; ++mb)
        #pragma unroll
        for (int j = 0; j < NJ; ++j) {
            float* c = acc[mb][j];
            *(float2*)&P[(size_t)(mb * 16 + r0) * D + j * 8 + c0]     = make_float2(c[0], c[1]);
            *(float2*)&P[(size_t)(mb * 16 + r0 + 8) * D + j * 8 + c0] = make_float2(c[2], c[3]);
        }
}

// ---------------------------------------------------------------------------
// Row-wise: h = [relu](sum partials) ; G' = h @ W^T, stored as G'^T bf16 hi/lo
// ---------------------------------------------------------------------------
template<int DIN, int DOUT, int KS, bool RELU, bool FROM_PART>
__global__ void __launch_bounds__(256)
row_gemm(const float* __restrict__ xsrc, const float* __restrict__ W) {
    __shared__ float Ws[DOUT * DIN];
    for (int i = threadIdx.x; i < DOUT * DIN; i += 256) Ws[i] = W[i];
    __syncthreads();

    const float* __restrict__ src = FROM_PART ? part_buf_dev : xsrc;
    const int r = blockIdx.x * 256 + threadIdx.x;

    float h[DIN];
    #pragma unroll
    for (int i4 = 0; i4 < DIN / 4; ++i4) {
        float4 v = *(const float4*)(src + (size_t)r * DIN + i4 * 4);
        h[4 * i4 + 0] = v.x; h[4 * i4 + 1] = v.y;
        h[4 * i4 + 2] = v.z; h[4 * i4 + 3] = v.w;
    }
    #pragma unroll
    for (int s = 1; s < KS; ++s)
        #pragma unroll
        for (int i4 = 0; i4 < DIN / 4; ++i4) {
            float4 v = *(const float4*)(src + ((size_t)s * NN + r) * DIN + i4 * 4);
            h[4 * i4 + 0] += v.x; h[4 * i4 + 1] += v.y;
            h[4 * i4 + 2] += v.z; h[4 * i4 + 3] += v.w;
        }
    if (RELU) {
        #pragma unroll
        for (int i = 0; i < DIN; ++i) h[i] = fmaxf(h[i], 0.0f);
    }

    #pragma unroll
    for (int j = 0; j < DOUT; ++j) {
        float a = 0.0f;
        const float* w = &Ws[j * DIN];
        #pragma unroll
        for (int i = 0; i < DIN; ++i) a = fmaf(h[i], w[i], a);
        __nv_bfloat16 hi = __float2bfloat16_rn(a);
        __nv_bfloat16 lo = __float2bfloat16_rn(a - __bfloat162float(hi));
        gt_hi_dev[(size_t)j * NN + r] = hi;
        gt_lo_dev[(size_t)j * NN + r] = lo;
    }
}

// ---------------------------------------------------------------------------
// Final reduce: out = sum of KSPLIT partials
// ---------------------------------------------------------------------------
__global__ void __launch_bounds__(256)
reduce_out(float* __restrict__ out) {
    const int idx = blockIdx.x * 256 + threadIdx.x;   // float4 index
    const float4* p4 = (const float4*)part_buf_dev;
    float4 a = p4[idx];
    #pragma unroll
    for (int s = 1; s < KSPLIT; ++s) {
        float4 b = p4[(size_t)s * (NN * 32 / 4) + idx];
        a.x += b.x; a.y += b.y; a.z += b.z; a.w += b.w;
    }
    ((float4*)out)[idx] = a;
}

// ---------------------------------------------------------------------------
// Launch
// ---------------------------------------------------------------------------
extern "C" void kernel_launch(void* const* d_in, const int* in_sizes, int n_in,
                              void* d_out, int out_size) {
    (void)in_sizes; (void)n_in; (void)out_size;
    const float* A  = (const float*)d_in[0];
    const float* X  = (const float*)d_in[1];
    const float* W1 = (const float*)d_in[2];
    const float* W2 = (const float*)d_in[3];
    const float* W3 = (const float*)d_in[4];
    const float* W4 = (const float*)d_in[5];
    float* out = (float*)d_out;

    constexpr int SMEM32 = 4 * 128 * 80 + 3 * 2 * 32 * 80;   // 56320
    constexpr int SMEM64 = 4 * 128 * 80 + 3 * 2 * 64 * 80;   // 71680
    cudaFuncSetAttribute(big_mma<32>, cudaFuncAttributeMaxDynamicSharedMemorySize, SMEM32);
    cudaFuncSetAttribute(big_mma<64>, cudaFuncAttributeMaxDynamicSharedMemorySize, SMEM64);

    const dim3 big_grid(NN / 128, KSPLIT);

    // Layer 1: G1 = X @ W1^T ; P = A @ G1
    row_gemm<32, 32, 1, false, false><<<NN / 256, 256>>>(X, W1);
    big_mma<32><<<big_grid, 128, SMEM32>>>(A);
    // Layer 2
    row_gemm<32, 64, KSPLIT, true, true><<<NN / 256, 256>>>(nullptr, W2);
    big_mma<64><<<big_grid, 128, SMEM64>>>(A);
    // Layer 3
    row_gemm<64, 64, KSPLIT, true, true><<<NN / 256, 256>>>(nullptr, W3);
    big_mma<64><<<big_grid, 128, SMEM64>>>(A);
    // Layer 4 (no relu on output)
    row_gemm<64, 32, KSPLIT, true, true><<<NN / 256, 256>>>(nullptr, W4);
    big_mma<32><<<big_grid, 128, SMEM32>>>(A);
    reduce_out<<<NN * 32 / 4 / 256, 256>>>(out);
}

// round 7
// speedup vs baseline: 1.2954x; 1.2954x over previous
#include <cuda_runtime.h>
#include <cuda_fp16.h>
#include <cstdint>

#define NN 8192
#define KSPLIT 16
#define KCH (NN / KSPLIT)          // 512
#define BK 64
#define NTILES (KCH / BK)          // 8

// ---------------------------------------------------------------------------
// Scratch (no cudaMalloc allowed)
// ---------------------------------------------------------------------------
__device__ __half a16_dev[(size_t)NN * NN];           // A in fp16 (128 MB)
__device__ __half gt_h_dev[64 * NN];                  // G^T hi  [D][NN], scaled
__device__ __half gt_l_dev[64 * NN];                  // G^T lo
__device__ float  g32_dev[NN * 64];                   // G fp32 (true scale)
__device__ float  part_buf_dev[(size_t)KSPLIT * NN * 64];  // 32 MB partials
__device__ unsigned g_max_dev[4];
__device__ float  g_scale_dev[4];
__device__ float  g_inv_dev[4];

// ---------------------------------------------------------------------------
// PTX helpers (plain sm_103-legal)
// ---------------------------------------------------------------------------
__device__ __forceinline__ uint32_t smem_u32(const void* p) {
    uint32_t a;
    asm("{ .reg .u64 t; cvta.to.shared.u64 t, %1; cvt.u32.u64 %0, t; }"
        : "=r"(a) : "l"(p));
    return a;
}
__device__ __forceinline__ void cp16(uint32_t dst, const void* src) {
    asm volatile("cp.async.cg.shared.global [%0], [%1], 16;\n"
                 :: "r"(dst), "l"(src));
}
#define CP_COMMIT() asm volatile("cp.async.commit_group;" ::: "memory")
#define CP_WAIT0()  asm volatile("cp.async.wait_group 0;" ::: "memory")
#define CP_WAIT1()  asm volatile("cp.async.wait_group 1;" ::: "memory")
#define SWZ128(x) ((x) ^ (((x) >> 3) & 0x70))

__device__ __forceinline__ void ldm4(uint32_t* a, uint32_t addr) {
    asm volatile("ldmatrix.sync.aligned.m8n8.x4.shared.b16 {%0,%1,%2,%3}, [%4];"
                 : "=r"(a[0]), "=r"(a[1]), "=r"(a[2]), "=r"(a[3]) : "r"(addr));
}
__device__ __forceinline__ void mma_f16(float* c, const uint32_t* a,
                                        uint32_t b0, uint32_t b1) {
    asm volatile(
        "mma.sync.aligned.m16n8k16.row.col.f32.f16.f16.f32 "
        "{%0,%1,%2,%3},{%4,%5,%6,%7},{%8,%9},{%0,%1,%2,%3};"
        : "+f"(c[0]), "+f"(c[1]), "+f"(c[2]), "+f"(c[3])
        : "r"(a[0]), "r"(a[1]), "r"(a[2]), "r"(a[3]), "r"(b0), "r"(b1));
}

// ---------------------------------------------------------------------------
// One-time A fp32 -> fp16 (A in [0,1), fits fp16 exactly to 2^-12 rel)
// ---------------------------------------------------------------------------
__global__ void __launch_bounds__(256)
split_a(const float* __restrict__ A) {
    size_t i = ((size_t)blockIdx.x * 256 + threadIdx.x) * 8;
    float4 v0 = *(const float4*)(A + i);
    float4 v1 = *(const float4*)(A + i + 4);
    __half2 h[4];
    h[0] = __floats2half2_rn(v0.x, v0.y);
    h[1] = __floats2half2_rn(v0.z, v0.w);
    h[2] = __floats2half2_rn(v1.x, v1.y);
    h[3] = __floats2half2_rn(v1.z, v1.w);
    *(uint4*)(a16_dev + i) = *(uint4*)h;
}

// ---------------------------------------------------------------------------
// init per-call state (graph replays must reset the maxes)
// ---------------------------------------------------------------------------
__global__ void init_max() {
    if (threadIdx.x < 4) g_max_dev[threadIdx.x] = 0u;
}

// ---------------------------------------------------------------------------
// Big GEMM: part[ks] = A16[:, kchunk] @ Gscaled[kchunk, :]   (2 fp16 terms)
//   BM=128, BK=64 (128B rows, XOR-swizzled), 8 warps (4 rowg x 2 colg).
//   All operands via cp.async: 3 stages, prefetch distance 2.
// ---------------------------------------------------------------------------
template<int D>
__global__ void __launch_bounds__(256, 2)
big_mma() {
    constexpr int NJ    = D / 16;          // n8-tiles per warp (n-extent D/2)
    constexpr int GPL   = D * 128;         // one G plane bytes
    constexpr int ATB   = 128 * 128;       // A tile bytes (16 KB)
    constexpr int STAGE = ATB + 2 * GPL;
    constexpr int GCHK  = D * 8;           // 16B chunks per G plane

    extern __shared__ __align__(1024) char smem[];
    const uint32_t sb = smem_u32(smem);
    const int tid  = threadIdx.x;
    const int wid  = tid >> 5;
    const int lane = tid & 31;
    const int rw   = wid >> 1;             // row group 0..3 (m-offset rw*32)
    const int cw   = wid & 1;              // col group 0..1 (n-offset cw*D/2)
    const size_t row0 = (size_t)blockIdx.x * 128;
    const size_t k0   = (size_t)blockIdx.y * KCH;

    auto load_tile = [&](int st, int kt) {
        const uint32_t base = sb + st * STAGE;
        const size_t   ke   = k0 + (size_t)kt * BK;
        #pragma unroll
        for (int p = 0; p < 4; ++p) {       // A: 128 rows x 8 chunks
            const int c = p * 256 + tid;
            const int r = c >> 3, ch = c & 7;
            cp16(base + SWZ128((uint32_t)(r * 128 + ch * 16)),
                 a16_dev + (row0 + r) * NN + ke + ch * 8);
        }
        #pragma unroll
        for (int p = 0; p < GCHK / 256; ++p) {  // G hi+lo: D rows x 8 chunks
            const int c = p * 256 + tid;
            const int r = c >> 3, ch = c & 7;
            const uint32_t so = SWZ128((uint32_t)(r * 128 + ch * 16));
            const size_t   go = (size_t)r * NN + ke + ch * 8;
            cp16(base + ATB + so,       gt_h_dev + go);
            cp16(base + ATB + GPL + so, gt_l_dev + go);
        }
    };

    float acc[2][NJ][4];
    #pragma unroll
    for (int mb = 0; mb < 2; ++mb)
        #pragma unroll
        for (int j = 0; j < NJ; ++j)
            #pragma unroll
            for (int q = 0; q < 4; ++q) acc[mb][j][q] = 0.0f;

    load_tile(0, 0); CP_COMMIT();
    load_tile(1, 1); CP_COMMIT();

    for (int kt = 0; kt < NTILES; ++kt) {
        if (kt == NTILES - 1) CP_WAIT0(); else CP_WAIT1();
        __syncthreads();

        if (kt + 2 < NTILES) { load_tile((kt + 2) % 3, kt + 2); CP_COMMIT(); }

        const uint32_t base = sb + (kt % 3) * STAGE;

        // A fragments: mb(2) x kk(4), m16k16 each
        uint32_t Ar[2][4][4];
        #pragma unroll
        for (int mb = 0; mb < 2; ++mb)
            #pragma unroll
            for (int kk = 0; kk < 4; ++kk)
                ldm4(Ar[mb][kk], base + SWZ128((uint32_t)(
                    (rw * 32 + mb * 16 + (lane & 15)) * 128
                    + kk * 32 + (lane >> 4) * 16)));

        const uint32_t gb = base + ATB;
        #pragma unroll
        for (int j = 0; j < NJ; ++j) {
            const uint32_t nrow = (uint32_t)((cw * (D / 2) + j * 8 + (lane & 7)) * 128
                                             + (lane >> 3) * 16);
            uint32_t bh[8], bl[8];
            ldm4(bh,     gb +       SWZ128(nrow));
            ldm4(bh + 4, gb +       SWZ128(nrow + 64));
            ldm4(bl,     gb + GPL + SWZ128(nrow));
            ldm4(bl + 4, gb + GPL + SWZ128(nrow + 64));
            #pragma unroll
            for (int mb = 0; mb < 2; ++mb) {
                float* c = acc[mb][j];
                #pragma unroll
                for (int kk = 0; kk < 4; ++kk) {
                    mma_f16(c, Ar[mb][kk], bh[2 * kk], bh[2 * kk + 1]);
                    mma_f16(c, Ar[mb][kk], bl[2 * kk], bl[2 * kk + 1]);
                }
            }
        }
    }

    // epilogue
    float* P = part_buf_dev
             + ((size_t)blockIdx.y * NN + row0 + rw * 32) * D + cw * (D / 2);
    const int r0 = lane >> 2;
    const int c0 = (lane & 3) * 2;
    #pragma unroll
    for (int mb = 0; mb < 2; ++mb)
        #pragma unroll
        for (int j = 0; j < NJ; ++j) {
            float* c = acc[mb][j];
            *(float2*)&P[(size_t)(mb * 16 + r0) * D + j * 8 + c0]     = make_float2(c[0], c[1]);
            *(float2*)&P[(size_t)(mb * 16 + r0 + 8) * D + j * 8 + c0] = make_float2(c[2], c[3]);
        }
}

// ---------------------------------------------------------------------------
// Row-wise: h = relu?(inv_prev * sum partials) ; g = h @ W^T -> g32 + max|g|
// ---------------------------------------------------------------------------
template<int DIN, int DOUT, int KS, bool RELU, int LAYER, int PREV>
__global__ void __launch_bounds__(256)
row_gemm(const float* __restrict__ xsrc, const float* __restrict__ W) {
    __shared__ float Ws[DOUT * DIN];
    for (int i = threadIdx.x; i < DOUT * DIN; i += 256) Ws[i] = W[i];
    __syncthreads();

    const float inv = (PREV >= 0) ? g_inv_dev[PREV] : 1.0f;
    const float* __restrict__ src = (PREV >= 0) ? part_buf_dev : xsrc;
    const int r = blockIdx.x * 256 + threadIdx.x;

    float h[DIN];
    #pragma unroll
    for (int i4 = 0; i4 < DIN / 4; ++i4) {
        float4 v = *(const float4*)(src + (size_t)r * DIN + i4 * 4);
        h[4 * i4 + 0] = v.x; h[4 * i4 + 1] = v.y;
        h[4 * i4 + 2] = v.z; h[4 * i4 + 3] = v.w;
    }
    #pragma unroll
    for (int s = 1; s < KS; ++s)
        #pragma unroll
        for (int i4 = 0; i4 < DIN / 4; ++i4) {
            float4 v = *(const float4*)(src + ((size_t)s * NN + r) * DIN + i4 * 4);
            h[4 * i4 + 0] += v.x; h[4 * i4 + 1] += v.y;
            h[4 * i4 + 2] += v.z; h[4 * i4 + 3] += v.w;
        }
    #pragma unroll
    for (int i = 0; i < DIN; ++i) {
        h[i] *= inv;
        if (RELU) h[i] = fmaxf(h[i], 0.0f);
    }

    float m = 0.0f;
    #pragma unroll
    for (int j = 0; j < DOUT; ++j) {
        float a = 0.0f;
        const float* w = &Ws[j * DIN];
        #pragma unroll
        for (int i = 0; i < DIN; ++i) a = fmaf(h[i], w[i], a);
        g32_dev[(size_t)r * DOUT + j] = a;
        m = fmaxf(m, fabsf(a));
    }
    #pragma unroll
    for (int o = 16; o; o >>= 1)
        m = fmaxf(m, __shfl_xor_sync(0xFFFFFFFFu, m, o));
    if ((threadIdx.x & 31) == 0)
        atomicMax(&g_max_dev[LAYER], __float_as_uint(m));
}

// ---------------------------------------------------------------------------
// Pick power-of-2 scale so max|g|*s <= 30000 (fp16-safe, exact inverse)
// ---------------------------------------------------------------------------
__global__ void mk_scale(int L) {
    float m = __uint_as_float(g_max_dev[L]);
    float s = 1.0f;
    if (m > 0.0f) s = exp2f(-ceilf(log2f(m / 30000.0f)));
    if (!(s > 0.0f) || isinf(s)) s = 1.0f;
    g_scale_dev[L] = s;
    g_inv_dev[L]   = 1.0f / s;
}

// ---------------------------------------------------------------------------
// Convert: G fp32 -> scaled fp16 hi/lo, transposed [D][NN]
// ---------------------------------------------------------------------------
template<int D>
__global__ void __launch_bounds__(256)
convert_g(int L) {
    const int r = blockIdx.x * 256 + threadIdx.x;
    const int j = blockIdx.y;
    const float s = g_scale_dev[L];
    const float v = g32_dev[(size_t)r * D + j] * s;
    const __half h = __float2half_rn(v);
    const __half l = __float2half_rn(v - __half2float(h));
    gt_h_dev[(size_t)j * NN + r] = h;
    gt_l_dev[(size_t)j * NN + r] = l;
}

// ---------------------------------------------------------------------------
// Final reduce: out = inv_s4 * sum of KSPLIT partials
// ---------------------------------------------------------------------------
__global__ void __launch_bounds__(256)
reduce_out(float* __restrict__ out) {
    const int idx = blockIdx.x * 256 + threadIdx.x;   // float4 index
    const float4* p4 = (const float4*)part_buf_dev;
    float4 a = p4[idx];
    #pragma unroll
    for (int s = 1; s < KSPLIT; ++s) {
        float4 b = p4[(size_t)s * (NN * 32 / 4) + idx];
        a.x += b.x; a.y += b.y; a.z += b.z; a.w += b.w;
    }
    const float inv = g_inv_dev[3];
    a.x *= inv; a.y *= inv; a.z *= inv; a.w *= inv;
    ((float4*)out)[idx] = a;
}

// ---------------------------------------------------------------------------
// Launch
// ---------------------------------------------------------------------------
extern "C" void kernel_launch(void* const* d_in, const int* in_sizes, int n_in,
                              void* d_out, int out_size) {
    (void)in_sizes; (void)n_in; (void)out_size;
    const float* A  = (const float*)d_in[0];
    const float* X  = (const float*)d_in[1];
    const float* W1 = (const float*)d_in[2];
    const float* W2 = (const float*)d_in[3];
    const float* W3 = (const float*)d_in[4];
    const float* W4 = (const float*)d_in[5];
    float* out = (float*)d_out;

    constexpr int SM32 = 3 * (16384 + 2 * 32 * 128);   // 73728
    constexpr int SM64 = 3 * (16384 + 2 * 64 * 128);   // 98304
    cudaFuncSetAttribute(big_mma<32>, cudaFuncAttributeMaxDynamicSharedMemorySize, SM32);
    cudaFuncSetAttribute(big_mma<64>, cudaFuncAttributeMaxDynamicSharedMemorySize, SM64);

    const dim3 big_grid(NN / 128, KSPLIT);

    init_max<<<1, 32>>>();
    split_a<<<NN * NN / 8 / 256, 256>>>(A);

    // Layer 1
    row_gemm<32, 32, 1, false, 0, -1><<<NN / 256, 256>>>(X, W1);
    mk_scale<<<1, 1>>>(0);
    convert_g<32><<<dim3(NN / 256, 32), 256>>>(0);
    big_mma<32><<<big_grid, 256, SM32>>>();
    // Layer 2
    row_gemm<32, 64, KSPLIT, true, 1, 0><<<NN / 256, 256>>>(nullptr, W2);
    mk_scale<<<1, 1>>>(1);
    convert_g<64><<<dim3(NN / 256, 64), 256>>>(1);
    big_mma<64><<<big_grid, 256, SM64>>>();
    // Layer 3
    row_gemm<64, 64, KSPLIT, true, 2, 1><<<NN / 256, 256>>>(nullptr, W3);
    mk_scale<<<1, 1>>>(2);
    convert_g<64><<<dim3(NN / 256, 64), 256>>>(2);
    big_mma<64><<<big_grid, 256, SM64>>>();
    // Layer 4 (relu applies to h3; output layer has no relu afterwards)
    row_gemm<64, 32, KSPLIT, true, 3, 2><<<NN / 256, 256>>>(nullptr, W4);
    mk_scale<<<1, 1>>>(3);
    convert_g<32><<<dim3(NN / 256, 32), 256>>>(3);
    big_mma<32><<<big_grid, 256, SM32>>>();

    reduce_out<<<NN * 32 / 4 / 256, 256>>>(out);
}

// round 8
// speedup vs baseline: 1.4745x; 1.1382x over previous
#include <cuda_runtime.h>
#include <cuda_fp16.h>
#include <cstdint>

#define NN 8192
#define KSPLIT 4
#define KCH (NN / KSPLIT)          // 2048
#define BK 64
#define NTILES (KCH / BK)          // 32

// ---------------------------------------------------------------------------
// Scratch (no cudaMalloc allowed)
// ---------------------------------------------------------------------------
__device__ __half a16_dev[(size_t)NN * NN];           // A in fp16 (128 MB)
__device__ __half gt_h_dev[64 * NN];                  // G^T hi  [D][NN], scaled
__device__ __half gt_l_dev[64 * NN];                  // G^T lo
__device__ float  g32_dev[NN * 64];                   // G fp32 (true scale)
__device__ float  part_buf_dev[(size_t)KSPLIT * NN * 64];  // 8 MB partials
__device__ unsigned g_max_dev[4];

// ---------------------------------------------------------------------------
// PTX helpers (plain sm_103-legal)
// ---------------------------------------------------------------------------
__device__ __forceinline__ uint32_t smem_u32(const void* p) {
    uint32_t a;
    asm("{ .reg .u64 t; cvta.to.shared.u64 t, %1; cvt.u32.u64 %0, t; }"
        : "=r"(a) : "l"(p));
    return a;
}
__device__ __forceinline__ void cp16(uint32_t dst, const void* src) {
    asm volatile("cp.async.cg.shared.global [%0], [%1], 16;\n"
                 :: "r"(dst), "l"(src));
}
#define CP_COMMIT() asm volatile("cp.async.commit_group;" ::: "memory")
#define CP_WAIT0()  asm volatile("cp.async.wait_group 0;" ::: "memory")
#define CP_WAIT1()  asm volatile("cp.async.wait_group 1;" ::: "memory")
#define SWZ128(x) ((x) ^ (((x) >> 3) & 0x70))

__device__ __forceinline__ void ldm4(uint32_t* a, uint32_t addr) {
    asm volatile("ldmatrix.sync.aligned.m8n8.x4.shared.b16 {%0,%1,%2,%3}, [%4];"
                 : "=r"(a[0]), "=r"(a[1]), "=r"(a[2]), "=r"(a[3]) : "r"(addr));
}
__device__ __forceinline__ void mma_f16(float* c, const uint32_t* a,
                                        uint32_t b0, uint32_t b1) {
    asm volatile(
        "mma.sync.aligned.m16n8k16.row.col.f32.f16.f16.f32 "
        "{%0,%1,%2,%3},{%4,%5,%6,%7},{%8,%9},{%0,%1,%2,%3};"
        : "+f"(c[0]), "+f"(c[1]), "+f"(c[2]), "+f"(c[3])
        : "r"(a[0]), "r"(a[1]), "r"(a[2]), "r"(a[3]), "r"(b0), "r"(b1));
}

// power-of-2 scale so max|g|*s <= 30000; identical math in every consumer
__device__ __forceinline__ float scale_of(int L) {
    float m = __uint_as_float(g_max_dev[L]);
    float s = 1.0f;
    if (m > 0.0f) s = exp2f(-ceilf(log2f(m / 30000.0f)));
    if (!(s > 0.0f) || isinf(s)) s = 1.0f;
    return s;
}

// ---------------------------------------------------------------------------
// One-time A fp32 -> fp16 ; block 0 also resets the per-layer maxes
// ---------------------------------------------------------------------------
__global__ void __launch_bounds__(256)
split_a(const float* __restrict__ A) {
    if (blockIdx.x == 0 && threadIdx.x < 4) g_max_dev[threadIdx.x] = 0u;
    size_t i = ((size_t)blockIdx.x * 256 + threadIdx.x) * 8;
    float4 v0 = *(const float4*)(A + i);
    float4 v1 = *(const float4*)(A + i + 4);
    __half2 h[4];
    h[0] = __floats2half2_rn(v0.x, v0.y);
    h[1] = __floats2half2_rn(v0.z, v0.w);
    h[2] = __floats2half2_rn(v1.x, v1.y);
    h[3] = __floats2half2_rn(v1.z, v1.w);
    *(uint4*)(a16_dev + i) = *(uint4*)h;
}

// ---------------------------------------------------------------------------
// Big GEMM: part[ks] = A16[:, kchunk] @ Gscaled[kchunk, :]   (2 fp16 terms)
//   BM=128, BK=64 (128B rows, XOR-swizzled), 8 warps (4 rowg x 2 colg).
//   All operands via cp.async: 3 stages, prefetch distance 2. Single wave.
// ---------------------------------------------------------------------------
template<int D>
__global__ void __launch_bounds__(256, 2)
big_mma() {
    constexpr int NJ    = D / 16;          // n8-tiles per warp (n-extent D/2)
    constexpr int GPL   = D * 128;         // one G plane bytes
    constexpr int ATB   = 128 * 128;       // A tile bytes (16 KB)
    constexpr int STAGE = ATB + 2 * GPL;
    constexpr int GCHK  = D * 8;           // 16B chunks per G plane

    extern __shared__ __align__(1024) char smem[];
    const uint32_t sb = smem_u32(smem);
    const int tid  = threadIdx.x;
    const int wid  = tid >> 5;
    const int lane = tid & 31;
    const int rw   = wid >> 1;             // row group 0..3 (m-offset rw*32)
    const int cw   = wid & 1;              // col group 0..1 (n-offset cw*D/2)
    const size_t row0 = (size_t)blockIdx.x * 128;
    const size_t k0   = (size_t)blockIdx.y * KCH;

    auto load_tile = [&](int st, int kt) {
        const uint32_t base = sb + st * STAGE;
        const size_t   ke   = k0 + (size_t)kt * BK;
        #pragma unroll
        for (int p = 0; p < 4; ++p) {       // A: 128 rows x 8 chunks
            const int c = p * 256 + tid;
            const int r = c >> 3, ch = c & 7;
            cp16(base + SWZ128((uint32_t)(r * 128 + ch * 16)),
                 a16_dev + (row0 + r) * NN + ke + ch * 8);
        }
        #pragma unroll
        for (int p = 0; p < GCHK / 256; ++p) {  // G hi+lo: D rows x 8 chunks
            const int c = p * 256 + tid;
            const int r = c >> 3, ch = c & 7;
            const uint32_t so = SWZ128((uint32_t)(r * 128 + ch * 16));
            const size_t   go = (size_t)r * NN + ke + ch * 8;
            cp16(base + ATB + so,       gt_h_dev + go);
            cp16(base + ATB + GPL + so, gt_l_dev + go);
        }
    };

    float acc[2][NJ][4];
    #pragma unroll
    for (int mb = 0; mb < 2; ++mb)
        #pragma unroll
        for (int j = 0; j < NJ; ++j)
            #pragma unroll
            for (int q = 0; q < 4; ++q) acc[mb][j][q] = 0.0f;

    load_tile(0, 0); CP_COMMIT();
    load_tile(1, 1); CP_COMMIT();

    for (int kt = 0; kt < NTILES; ++kt) {
        if (kt == NTILES - 1) CP_WAIT0(); else CP_WAIT1();
        __syncthreads();

        if (kt + 2 < NTILES) { load_tile((kt + 2) % 3, kt + 2); CP_COMMIT(); }

        const uint32_t base = sb + (kt % 3) * STAGE;

        // A fragments: mb(2) x kk(4), m16k16 each
        uint32_t Ar[2][4][4];
        #pragma unroll
        for (int mb = 0; mb < 2; ++mb)
            #pragma unroll
            for (int kk = 0; kk < 4; ++kk)
                ldm4(Ar[mb][kk], base + SWZ128((uint32_t)(
                    (rw * 32 + mb * 16 + (lane & 15)) * 128
                    + kk * 32 + (lane >> 4) * 16)));

        const uint32_t gb = base + ATB;
        #pragma unroll
        for (int j = 0; j < NJ; ++j) {
            const uint32_t nrow = (uint32_t)((cw * (D / 2) + j * 8 + (lane & 7)) * 128
                                             + (lane >> 3) * 16);
            uint32_t bh[8], bl[8];
            ldm4(bh,     gb +       SWZ128(nrow));
            ldm4(bh + 4, gb +       SWZ128(nrow + 64));
            ldm4(bl,     gb + GPL + SWZ128(nrow));
            ldm4(bl + 4, gb + GPL + SWZ128(nrow + 64));
            #pragma unroll
            for (int mb = 0; mb < 2; ++mb) {
                float* c = acc[mb][j];
                #pragma unroll
                for (int kk = 0; kk < 4; ++kk) {
                    mma_f16(c, Ar[mb][kk], bh[2 * kk], bh[2 * kk + 1]);
                    mma_f16(c, Ar[mb][kk], bl[2 * kk], bl[2 * kk + 1]);
                }
            }
        }
    }

    // epilogue
    float* P = part_buf_dev
             + ((size_t)blockIdx.y * NN + row0 + rw * 32) * D + cw * (D / 2);
    const int r0 = lane >> 2;
    const int c0 = (lane & 3) * 2;
    #pragma unroll
    for (int mb = 0; mb < 2; ++mb)
        #pragma unroll
        for (int j = 0; j < NJ; ++j) {
            float* c = acc[mb][j];
            *(float2*)&P[(size_t)(mb * 16 + r0) * D + j * 8 + c0]     = make_float2(c[0], c[1]);
            *(float2*)&P[(size_t)(mb * 16 + r0 + 8) * D + j * 8 + c0] = make_float2(c[2], c[3]);
        }
}

// ---------------------------------------------------------------------------
// Row-wise: h = relu?(inv_prev * sum partials) ; g = h @ W^T -> g32 + max|g|
// ---------------------------------------------------------------------------
template<int DIN, int DOUT, int KS, bool RELU, int LAYER, int PREV>
__global__ void __launch_bounds__(256)
row_gemm(const float* __restrict__ xsrc, const float* __restrict__ W) {
    __shared__ float Ws[DOUT * DIN];
    for (int i = threadIdx.x; i < DOUT * DIN; i += 256) Ws[i] = W[i];
    __syncthreads();

    const float inv = (PREV >= 0) ? (1.0f / scale_of(PREV)) : 1.0f;
    const float* __restrict__ src = (PREV >= 0) ? part_buf_dev : xsrc;
    const int r = blockIdx.x * 256 + threadIdx.x;

    float h[DIN];
    #pragma unroll
    for (int i4 = 0; i4 < DIN / 4; ++i4) {
        float4 v = *(const float4*)(src + (size_t)r * DIN + i4 * 4);
        h[4 * i4 + 0] = v.x; h[4 * i4 + 1] = v.y;
        h[4 * i4 + 2] = v.z; h[4 * i4 + 3] = v.w;
    }
    #pragma unroll
    for (int s = 1; s < KS; ++s)
        #pragma unroll
        for (int i4 = 0; i4 < DIN / 4; ++i4) {
            float4 v = *(const float4*)(src + ((size_t)s * NN + r) * DIN + i4 * 4);
            h[4 * i4 + 0] += v.x; h[4 * i4 + 1] += v.y;
            h[4 * i4 + 2] += v.z; h[4 * i4 + 3] += v.w;
        }
    #pragma unroll
    for (int i = 0; i < DIN; ++i) {
        h[i] *= inv;
        if (RELU) h[i] = fmaxf(h[i], 0.0f);
    }

    float m = 0.0f;
    #pragma unroll
    for (int j = 0; j < DOUT; ++j) {
        float a = 0.0f;
        const float* w = &Ws[j * DIN];
        #pragma unroll
        for (int i = 0; i < DIN; ++i) a = fmaf(h[i], w[i], a);
        g32_dev[(size_t)r * DOUT + j] = a;
        m = fmaxf(m, fabsf(a));
    }
    #pragma unroll
    for (int o = 16; o; o >>= 1)
        m = fmaxf(m, __shfl_xor_sync(0xFFFFFFFFu, m, o));
    if ((threadIdx.x & 31) == 0)
        atomicMax(&g_max_dev[LAYER], __float_as_uint(m));
}

// ---------------------------------------------------------------------------
// Convert: G fp32 -> scaled fp16 hi/lo, transposed [D][NN] (scale inlined)
// ---------------------------------------------------------------------------
template<int D>
__global__ void __launch_bounds__(256)
convert_g(int L) {
    const int r = blockIdx.x * 256 + threadIdx.x;
    const int j = blockIdx.y;
    const float s = scale_of(L);
    const float v = g32_dev[(size_t)r * D + j] * s;
    const __half h = __float2half_rn(v);
    const __half l = __float2half_rn(v - __half2float(h));
    gt_h_dev[(size_t)j * NN + r] = h;
    gt_l_dev[(size_t)j * NN + r] = l;
}

// ---------------------------------------------------------------------------
// Final reduce: out = inv_s4 * sum of KSPLIT partials
// ---------------------------------------------------------------------------
__global__ void __launch_bounds__(256)
reduce_out(float* __restrict__ out) {
    const int idx = blockIdx.x * 256 + threadIdx.x;   // float4 index
    const float4* p4 = (const float4*)part_buf_dev;
    float4 a = p4[idx];
    #pragma unroll
    for (int s = 1; s < KSPLIT; ++s) {
        float4 b = p4[(size_t)s * (NN * 32 / 4) + idx];
        a.x += b.x; a.y += b.y; a.z += b.z; a.w += b.w;
    }
    const float inv = 1.0f / scale_of(3);
    a.x *= inv; a.y *= inv; a.z *= inv; a.w *= inv;
    ((float4*)out)[idx] = a;
}

// ---------------------------------------------------------------------------
// Launch
// ---------------------------------------------------------------------------
extern "C" void kernel_launch(void* const* d_in, const int* in_sizes, int n_in,
                              void* d_out, int out_size) {
    (void)in_sizes; (void)n_in; (void)out_size;
    const float* A  = (const float*)d_in[0];
    const float* X  = (const float*)d_in[1];
    const float* W1 = (const float*)d_in[2];
    const float* W2 = (const float*)d_in[3];
    const float* W3 = (const float*)d_in[4];
    const float* W4 = (const float*)d_in[5];
    float* out = (float*)d_out;

    constexpr int SM32 = 3 * (16384 + 2 * 32 * 128);   // 73728
    constexpr int SM64 = 3 * (16384 + 2 * 64 * 128);   // 98304
    cudaFuncSetAttribute(big_mma<32>, cudaFuncAttributeMaxDynamicSharedMemorySize, SM32);
    cudaFuncSetAttribute(big_mma<64>, cudaFuncAttributeMaxDynamicSharedMemorySize, SM64);

    const dim3 big_grid(NN / 128, KSPLIT);   // 64 x 4 = 256 CTAs (single wave)

    split_a<<<NN * NN / 8 / 256, 256>>>(A);

    // Layer 1
    row_gemm<32, 32, 1, false, 0, -1><<<NN / 256, 256>>>(X, W1);
    convert_g<32><<<dim3(NN / 256, 32), 256>>>(0);
    big_mma<32><<<big_grid, 256, SM32>>>();
    // Layer 2
    row_gemm<32, 64, KSPLIT, true, 1, 0><<<NN / 256, 256>>>(nullptr, W2);
    convert_g<64><<<dim3(NN / 256, 64), 256>>>(1);
    big_mma<64><<<big_grid, 256, SM64>>>();
    // Layer 3
    row_gemm<64, 64, KSPLIT, true, 2, 1><<<NN / 256, 256>>>(nullptr, W3);
    convert_g<64><<<dim3(NN / 256, 64), 256>>>(2);
    big_mma<64><<<big_grid, 256, SM64>>>();
    // Layer 4 (relu applies to h3; output layer has no relu afterwards)
    row_gemm<64, 32, KSPLIT, true, 3, 2><<<NN / 256, 256>>>(nullptr, W4);
    convert_g<32><<<dim3(NN / 256, 32), 256>>>(3);
    big_mma<32><<<big_grid, 256, SM32>>>();

    reduce_out<<<NN * 32 / 4 / 256, 256>>>(out);
}

// round 9
// speedup vs baseline: 1.7095x; 1.1594x over previous
#include <cuda_runtime.h>
#include <cuda_fp16.h>
#include <cstdint>

#define NN 8192
#define KSPLIT 4
#define KCH (NN / KSPLIT)          // 2048
#define BK 64
#define NTILES (KCH / BK)          // 32

// ---------------------------------------------------------------------------
// Scratch (no cudaMalloc allowed)
// ---------------------------------------------------------------------------
__device__ __half a16_dev[(size_t)NN * NN];           // A in fp16 (128 MB)
__device__ __half gt_h_dev[64 * NN];                  // G^T hi [D][NN], scaled
__device__ float  g32_dev[NN * 64];                   // G fp32 (true scale)
__device__ float  part_buf_dev[(size_t)KSPLIT * NN * 64];  // 8 MB partials
__device__ unsigned g_max_dev[4];

// ---------------------------------------------------------------------------
// PTX helpers (plain sm_103-legal)
// ---------------------------------------------------------------------------
__device__ __forceinline__ uint32_t smem_u32(const void* p) {
    uint32_t a;
    asm("{ .reg .u64 t; cvta.to.shared.u64 t, %1; cvt.u32.u64 %0, t; }"
        : "=r"(a) : "l"(p));
    return a;
}
__device__ __forceinline__ void cp16(uint32_t dst, const void* src) {
    asm volatile("cp.async.cg.shared.global [%0], [%1], 16;\n"
                 :: "r"(dst), "l"(src));
}
#define CP_COMMIT() asm volatile("cp.async.commit_group;" ::: "memory")
#define CP_WAIT0()  asm volatile("cp.async.wait_group 0;" ::: "memory")
#define CP_WAIT1()  asm volatile("cp.async.wait_group 1;" ::: "memory")
#define SWZ128(x) ((x) ^ (((x) >> 3) & 0x70))

__device__ __forceinline__ void ldm4(uint32_t* a, uint32_t addr) {
    asm volatile("ldmatrix.sync.aligned.m8n8.x4.shared.b16 {%0,%1,%2,%3}, [%4];"
                 : "=r"(a[0]), "=r"(a[1]), "=r"(a[2]), "=r"(a[3]) : "r"(addr));
}
__device__ __forceinline__ void mma_f16(float* c, const uint32_t* a,
                                        uint32_t b0, uint32_t b1) {
    asm volatile(
        "mma.sync.aligned.m16n8k16.row.col.f32.f16.f16.f32 "
        "{%0,%1,%2,%3},{%4,%5,%6,%7},{%8,%9},{%0,%1,%2,%3};"
        : "+f"(c[0]), "+f"(c[1]), "+f"(c[2]), "+f"(c[3])
        : "r"(a[0]), "r"(a[1]), "r"(a[2]), "r"(a[3]), "r"(b0), "r"(b1));
}

// power-of-2 scale so max|g|*s <= 30000; identical math in every consumer
__device__ __forceinline__ float scale_of(int L) {
    float m = __uint_as_float(g_max_dev[L]);
    float s = 1.0f;
    if (m > 0.0f) s = exp2f(-ceilf(log2f(m / 30000.0f)));
    if (!(s > 0.0f) || isinf(s)) s = 1.0f;
    return s;
}

// ---------------------------------------------------------------------------
// One-time A fp32 -> fp16 ; block 0 also resets the per-layer maxes
// ---------------------------------------------------------------------------
__global__ void __launch_bounds__(256)
split_a(const float* __restrict__ A) {
    if (blockIdx.x == 0 && threadIdx.x < 4) g_max_dev[threadIdx.x] = 0u;
    size_t i = ((size_t)blockIdx.x * 256 + threadIdx.x) * 8;
    float4 v0 = *(const float4*)(A + i);
    float4 v1 = *(const float4*)(A + i + 4);
    __half2 h[4];
    h[0] = __floats2half2_rn(v0.x, v0.y);
    h[1] = __floats2half2_rn(v0.z, v0.w);
    h[2] = __floats2half2_rn(v1.x, v1.y);
    h[3] = __floats2half2_rn(v1.z, v1.w);
    *(uint4*)(a16_dev + i) = *(uint4*)h;
}

// ---------------------------------------------------------------------------
// Big GEMM: part[ks] = A16[:, kchunk] @ Gscaled_hi[kchunk, :]  (1 fp16 term)
//   BM=128, BK=64 (128B rows, XOR-swizzled), 8 warps (4 rowg x 2 colg).
//   All operands via cp.async: 3 stages, prefetch distance 2. Single wave.
// ---------------------------------------------------------------------------
template<int D>
__global__ void __launch_bounds__(256, 2)
big_mma() {
    constexpr int NJ    = D / 16;          // n8-tiles per warp (n-extent D/2)
    constexpr int GPL   = D * 128;         // G plane bytes (hi only)
    constexpr int ATB   = 128 * 128;       // A tile bytes (16 KB)
    constexpr int STAGE = ATB + GPL;
    constexpr int GCHK  = D * 8;           // 16B chunks in G plane

    extern __shared__ __align__(1024) char smem[];
    const uint32_t sb = smem_u32(smem);
    const int tid  = threadIdx.x;
    const int wid  = tid >> 5;
    const int lane = tid & 31;
    const int rw   = wid >> 1;             // row group 0..3 (m-offset rw*32)
    const int cw   = wid & 1;              // col group 0..1 (n-offset cw*D/2)
    const size_t row0 = (size_t)blockIdx.x * 128;
    const size_t k0   = (size_t)blockIdx.y * KCH;

    auto load_tile = [&](int st, int kt) {
        const uint32_t base = sb + st * STAGE;
        const size_t   ke   = k0 + (size_t)kt * BK;
        #pragma unroll
        for (int p = 0; p < 4; ++p) {       // A: 128 rows x 8 chunks
            const int c = p * 256 + tid;
            const int r = c >> 3, ch = c & 7;
            cp16(base + SWZ128((uint32_t)(r * 128 + ch * 16)),
                 a16_dev + (row0 + r) * NN + ke + ch * 8);
        }
        #pragma unroll
        for (int p = 0; p < GCHK / 256; ++p) {  // G hi: D rows x 8 chunks
            const int c = p * 256 + tid;
            const int r = c >> 3, ch = c & 7;
            cp16(base + ATB + SWZ128((uint32_t)(r * 128 + ch * 16)),
                 gt_h_dev + (size_t)r * NN + ke + ch * 8);
        }
    };

    float acc[2][NJ][4];
    #pragma unroll
    for (int mb = 0; mb < 2; ++mb)
        #pragma unroll
        for (int j = 0; j < NJ; ++j)
            #pragma unroll
            for (int q = 0; q < 4; ++q) acc[mb][j][q] = 0.0f;

    load_tile(0, 0); CP_COMMIT();
    load_tile(1, 1); CP_COMMIT();

    for (int kt = 0; kt < NTILES; ++kt) {
        if (kt == NTILES - 1) CP_WAIT0(); else CP_WAIT1();
        __syncthreads();

        if (kt + 2 < NTILES) { load_tile((kt + 2) % 3, kt + 2); CP_COMMIT(); }

        const uint32_t base = sb + (kt % 3) * STAGE;

        // A fragments: mb(2) x kk(4), m16k16 each
        uint32_t Ar[2][4][4];
        #pragma unroll
        for (int mb = 0; mb < 2; ++mb)
            #pragma unroll
            for (int kk = 0; kk < 4; ++kk)
                ldm4(Ar[mb][kk], base + SWZ128((uint32_t)(
                    (rw * 32 + mb * 16 + (lane & 15)) * 128
                    + kk * 32 + (lane >> 4) * 16)));

        const uint32_t gb = base + ATB;
        #pragma unroll
        for (int j = 0; j < NJ; ++j) {
            const uint32_t nrow = (uint32_t)((cw * (D / 2) + j * 8 + (lane & 7)) * 128
                                             + (lane >> 3) * 16);
            uint32_t bh[8];
            ldm4(bh,     gb + SWZ128(nrow));
            ldm4(bh + 4, gb + SWZ128(nrow + 64));
            #pragma unroll
            for (int mb = 0; mb < 2; ++mb) {
                float* c = acc[mb][j];
                #pragma unroll
                for (int kk = 0; kk < 4; ++kk)
                    mma_f16(c, Ar[mb][kk], bh[2 * kk], bh[2 * kk + 1]);
            }
        }
    }

    // epilogue
    float* P = part_buf_dev
             + ((size_t)blockIdx.y * NN + row0 + rw * 32) * D + cw * (D / 2);
    const int r0 = lane >> 2;
    const int c0 = (lane & 3) * 2;
    #pragma unroll
    for (int mb = 0; mb < 2; ++mb)
        #pragma unroll
        for (int j = 0; j < NJ; ++j) {
            float* c = acc[mb][j];
            *(float2*)&P[(size_t)(mb * 16 + r0) * D + j * 8 + c0]     = make_float2(c[0], c[1]);
            *(float2*)&P[(size_t)(mb * 16 + r0 + 8) * D + j * 8 + c0] = make_float2(c[2], c[3]);
        }
}

// ---------------------------------------------------------------------------
// Row-wise: h = relu?(inv_prev * sum partials) ; g = h @ W^T -> g32 + max|g|
// ---------------------------------------------------------------------------
template<int DIN, int DOUT, int KS, bool RELU, int LAYER, int PREV>
__global__ void __launch_bounds__(256)
row_gemm(const float* __restrict__ xsrc, const float* __restrict__ W) {
    __shared__ float Ws[DOUT * DIN];
    for (int i = threadIdx.x; i < DOUT * DIN; i += 256) Ws[i] = W[i];
    __syncthreads();

    const float inv = (PREV >= 0) ? (1.0f / scale_of(PREV)) : 1.0f;
    const float* __restrict__ src = (PREV >= 0) ? part_buf_dev : xsrc;
    const int r = blockIdx.x * 256 + threadIdx.x;

    float h[DIN];
    #pragma unroll
    for (int i4 = 0; i4 < DIN / 4; ++i4) {
        float4 v = *(const float4*)(src + (size_t)r * DIN + i4 * 4);
        h[4 * i4 + 0] = v.x; h[4 * i4 + 1] = v.y;
        h[4 * i4 + 2] = v.z; h[4 * i4 + 3] = v.w;
    }
    #pragma unroll
    for (int s = 1; s < KS; ++s)
        #pragma unroll
        for (int i4 = 0; i4 < DIN / 4; ++i4) {
            float4 v = *(const float4*)(src + ((size_t)s * NN + r) * DIN + i4 * 4);
            h[4 * i4 + 0] += v.x; h[4 * i4 + 1] += v.y;
            h[4 * i4 + 2] += v.z; h[4 * i4 + 3] += v.w;
        }
    #pragma unroll
    for (int i = 0; i < DIN; ++i) {
        h[i] *= inv;
        if (RELU) h[i] = fmaxf(h[i], 0.0f);
    }

    float m = 0.0f;
    #pragma unroll
    for (int j = 0; j < DOUT; ++j) {
        float a = 0.0f;
        const float* w = &Ws[j * DIN];
        #pragma unroll
        for (int i = 0; i < DIN; ++i) a = fmaf(h[i], w[i], a);
        g32_dev[(size_t)r * DOUT + j] = a;
        m = fmaxf(m, fabsf(a));
    }
    #pragma unroll
    for (int o = 16; o; o >>= 1)
        m = fmaxf(m, __shfl_xor_sync(0xFFFFFFFFu, m, o));
    if ((threadIdx.x & 31) == 0)
        atomicMax(&g_max_dev[LAYER], __float_as_uint(m));
}

// ---------------------------------------------------------------------------
// Convert: G fp32 -> scaled fp16 (hi only), transposed [D][NN]
// ---------------------------------------------------------------------------
template<int D>
__global__ void __launch_bounds__(256)
convert_g(int L) {
    const int r = blockIdx.x * 256 + threadIdx.x;
    const int j = blockIdx.y;
    const float s = scale_of(L);
    gt_h_dev[(size_t)j * NN + r] =
        __float2half_rn(g32_dev[(size_t)r * D + j] * s);
}

// ---------------------------------------------------------------------------
// Final reduce: out = inv_s4 * sum of KSPLIT partials
// ---------------------------------------------------------------------------
__global__ void __launch_bounds__(256)
reduce_out(float* __restrict__ out) {
    const int idx = blockIdx.x * 256 + threadIdx.x;   // float4 index
    const float4* p4 = (const float4*)part_buf_dev;
    float4 a = p4[idx];
    #pragma unroll
    for (int s = 1; s < KSPLIT; ++s) {
        float4 b = p4[(size_t)s * (NN * 32 / 4) + idx];
        a.x += b.x; a.y += b.y; a.z += b.z; a.w += b.w;
    }
    const float inv = 1.0f / scale_of(3);
    a.x *= inv; a.y *= inv; a.z *= inv; a.w *= inv;
    ((float4*)out)[idx] = a;
}

// ---------------------------------------------------------------------------
// Launch
// ---------------------------------------------------------------------------
extern "C" void kernel_launch(void* const* d_in, const int* in_sizes, int n_in,
                              void* d_out, int out_size) {
    (void)in_sizes; (void)n_in; (void)out_size;
    const float* A  = (const float*)d_in[0];
    const float* X  = (const float*)d_in[1];
    const float* W1 = (const float*)d_in[2];
    const float* W2 = (const float*)d_in[3];
    const float* W3 = (const float*)d_in[4];
    const float* W4 = (const float*)d_in[5];
    float* out = (float*)d_out;

    constexpr int SM32 = 3 * (16384 + 32 * 128);   // 61440
    constexpr int SM64 = 3 * (16384 + 64 * 128);   // 73728
    cudaFuncSetAttribute(big_mma<32>, cudaFuncAttributeMaxDynamicSharedMemorySize, SM32);
    cudaFuncSetAttribute(big_mma<64>, cudaFuncAttributeMaxDynamicSharedMemorySize, SM64);

    const dim3 big_grid(NN / 128, KSPLIT);   // 64 x 4 = 256 CTAs (single wave)

    split_a<<<NN * NN / 8 / 256, 256>>>(A);

    // Layer 1
    row_gemm<32, 32, 1, false, 0, -1><<<NN / 256, 256>>>(X, W1);
    convert_g<32><<<dim3(NN / 256, 32), 256>>>(0);
    big_mma<32><<<big_grid, 256, SM32>>>();
    // Layer 2
    row_gemm<32, 64, KSPLIT, true, 1, 0><<<NN / 256, 256>>>(nullptr, W2);
    convert_g<64><<<dim3(NN / 256, 64), 256>>>(1);
    big_mma<64><<<big_grid, 256, SM64>>>();
    // Layer 3
    row_gemm<64, 64, KSPLIT, true, 2, 1><<<NN / 256, 256>>>(nullptr, W3);
    convert_g<64><<<dim3(NN / 256, 64), 256>>>(2);
    big_mma<64><<<big_grid, 256, SM64>>>();
    // Layer 4 (relu applies to h3; output layer has no relu afterwards)
    row_gemm<64, 32, KSPLIT, true, 3, 2><<<NN / 256, 256>>>(nullptr, W4);
    convert_g<32><<<dim3(NN / 256, 32), 256>>>(3);
    big_mma<32><<<big_grid, 256, SM32>>>();

    reduce_out<<<NN * 32 / 4 / 256, 256>>>(out);
}

// round 10
// speedup vs baseline: 1.9132x; 1.1192x over previous
#include <cuda_runtime.h>
#include <cuda_fp16.h>
#include <cstdint>

#define NN 8192
#define KSPLIT 4
#define KCH (NN / KSPLIT)          // 2048
#define BK 64
#define NTILES (KCH / BK)          // 32

// ---------------------------------------------------------------------------
// Scratch (no cudaMalloc allowed)
// ---------------------------------------------------------------------------
__device__ __half a16_dev[(size_t)NN * NN];           // A in fp16 (128 MB)
__device__ __half gt_h_dev[64 * NN];                  // G^T hi [D][NN], scaled
__device__ float  gt32_dev[64 * NN];                  // G^T fp32 (true scale)
__device__ float  part_buf_dev[(size_t)KSPLIT * NN * 64];  // 8 MB partials
__device__ unsigned g_max_dev[4];

// ---------------------------------------------------------------------------
// PTX helpers (plain sm_103-legal)
// ---------------------------------------------------------------------------
__device__ __forceinline__ uint32_t smem_u32(const void* p) {
    uint32_t a;
    asm("{ .reg .u64 t; cvta.to.shared.u64 t, %1; cvt.u32.u64 %0, t; }"
        : "=r"(a) : "l"(p));
    return a;
}
__device__ __forceinline__ void cp16(uint32_t dst, const void* src) {
    asm volatile("cp.async.cg.shared.global [%0], [%1], 16;\n"
                 :: "r"(dst), "l"(src));
}
#define CP_COMMIT() asm volatile("cp.async.commit_group;" ::: "memory")
#define CP_WAIT0()  asm volatile("cp.async.wait_group 0;" ::: "memory")
#define CP_WAIT1()  asm volatile("cp.async.wait_group 1;" ::: "memory")
#define CP_WAIT2()  asm volatile("cp.async.wait_group 2;" ::: "memory")
#define SWZ128(x) ((x) ^ (((x) >> 3) & 0x70))

__device__ __forceinline__ void ldm4(uint32_t* a, uint32_t addr) {
    asm volatile("ldmatrix.sync.aligned.m8n8.x4.shared.b16 {%0,%1,%2,%3}, [%4];"
                 : "=r"(a[0]), "=r"(a[1]), "=r"(a[2]), "=r"(a[3]) : "r"(addr));
}
__device__ __forceinline__ void mma_f16(float* c, const uint32_t* a,
                                        uint32_t b0, uint32_t b1) {
    asm volatile(
        "mma.sync.aligned.m16n8k16.row.col.f32.f16.f16.f32 "
        "{%0,%1,%2,%3},{%4,%5,%6,%7},{%8,%9},{%0,%1,%2,%3};"
        : "+f"(c[0]), "+f"(c[1]), "+f"(c[2]), "+f"(c[3])
        : "r"(a[0]), "r"(a[1]), "r"(a[2]), "r"(a[3]), "r"(b0), "r"(b1));
}

// power-of-2 scale so max|g|*s <= 30000; identical math in every consumer
__device__ __forceinline__ float scale_of(int L) {
    float m = __uint_as_float(g_max_dev[L]);
    float s = 1.0f;
    if (m > 0.0f) s = exp2f(-ceilf(log2f(m / 30000.0f)));
    if (!(s > 0.0f) || isinf(s)) s = 1.0f;
    return s;
}

// ---------------------------------------------------------------------------
// One-time A fp32 -> fp16 ; block 0 also resets the per-layer maxes
// ---------------------------------------------------------------------------
__global__ void __launch_bounds__(256)
split_a(const float* __restrict__ A) {
    if (blockIdx.x == 0 && threadIdx.x < 4) g_max_dev[threadIdx.x] = 0u;
    size_t i = ((size_t)blockIdx.x * 256 + threadIdx.x) * 8;
    float4 v0 = *(const float4*)(A + i);
    float4 v1 = *(const float4*)(A + i + 4);
    __half2 h[4];
    h[0] = __floats2half2_rn(v0.x, v0.y);
    h[1] = __floats2half2_rn(v0.z, v0.w);
    h[2] = __floats2half2_rn(v1.x, v1.y);
    h[3] = __floats2half2_rn(v1.z, v1.w);
    *(uint4*)(a16_dev + i) = *(uint4*)h;
}

// ---------------------------------------------------------------------------
// Big GEMM: part[ks] = A16[:, kchunk] @ Gscaled_hi[kchunk, :]  (1 fp16 term)
//   BM=128, BK=64 (128B rows, XOR-swizzled), 8 warps (4 rowg x 2 colg).
//   4-stage cp.async pipeline, prefetch distance 3. Single wave.
// ---------------------------------------------------------------------------
template<int D>
__global__ void __launch_bounds__(256, 2)
big_mma() {
    constexpr int NJ    = D / 16;          // n8-tiles per warp (n-extent D/2)
    constexpr int GPL   = D * 128;         // G plane bytes (hi only)
    constexpr int ATB   = 128 * 128;       // A tile bytes (16 KB)
    constexpr int STAGE = ATB + GPL;
    constexpr int GCHK  = D * 8;           // 16B chunks in G plane

    extern __shared__ __align__(1024) char smem[];
    const uint32_t sb = smem_u32(smem);
    const int tid  = threadIdx.x;
    const int wid  = tid >> 5;
    const int lane = tid & 31;
    const int rw   = wid >> 1;             // row group 0..3 (m-offset rw*32)
    const int cw   = wid & 1;              // col group 0..1 (n-offset cw*D/2)
    const size_t row0 = (size_t)blockIdx.x * 128;
    const size_t k0   = (size_t)blockIdx.y * KCH;

    auto load_tile = [&](int st, int kt) {
        const uint32_t base = sb + st * STAGE;
        const size_t   ke   = k0 + (size_t)kt * BK;
        #pragma unroll
        for (int p = 0; p < 4; ++p) {       // A: 128 rows x 8 chunks
            const int c = p * 256 + tid;
            const int r = c >> 3, ch = c & 7;
            cp16(base + SWZ128((uint32_t)(r * 128 + ch * 16)),
                 a16_dev + (row0 + r) * NN + ke + ch * 8);
        }
        #pragma unroll
        for (int p = 0; p < GCHK / 256; ++p) {  // G hi: D rows x 8 chunks
            const int c = p * 256 + tid;
            const int r = c >> 3, ch = c & 7;
            cp16(base + ATB + SWZ128((uint32_t)(r * 128 + ch * 16)),
                 gt_h_dev + (size_t)r * NN + ke + ch * 8);
        }
    };

    float acc[2][NJ][4];
    #pragma unroll
    for (int mb = 0; mb < 2; ++mb)
        #pragma unroll
        for (int j = 0; j < NJ; ++j)
            #pragma unroll
            for (int q = 0; q < 4; ++q) acc[mb][j][q] = 0.0f;

    // prologue: tiles 0,1,2 in flight (distance 3)
    load_tile(0, 0); CP_COMMIT();
    load_tile(1, 1); CP_COMMIT();
    load_tile(2, 2); CP_COMMIT();

    for (int kt = 0; kt < NTILES; ++kt) {
        if (kt < NTILES - 2)       CP_WAIT2();
        else if (kt == NTILES - 2) CP_WAIT1();
        else                       CP_WAIT0();
        __syncthreads();

        if (kt + 3 < NTILES) { load_tile((kt + 3) & 3, kt + 3); CP_COMMIT(); }

        const uint32_t base = sb + (kt & 3) * STAGE;

        // A fragments: mb(2) x kk(4), m16k16 each
        uint32_t Ar[2][4][4];
        #pragma unroll
        for (int mb = 0; mb < 2; ++mb)
            #pragma unroll
            for (int kk = 0; kk < 4; ++kk)
                ldm4(Ar[mb][kk], base + SWZ128((uint32_t)(
                    (rw * 32 + mb * 16 + (lane & 15)) * 128
                    + kk * 32 + (lane >> 4) * 16)));

        const uint32_t gb = base + ATB;
        #pragma unroll
        for (int j = 0; j < NJ; ++j) {
            const uint32_t nrow = (uint32_t)((cw * (D / 2) + j * 8 + (lane & 7)) * 128
                                             + (lane >> 3) * 16);
            uint32_t bh[8];
            ldm4(bh,     gb + SWZ128(nrow));
            ldm4(bh + 4, gb + SWZ128(nrow + 64));
            #pragma unroll
            for (int mb = 0; mb < 2; ++mb) {
                float* c = acc[mb][j];
                #pragma unroll
                for (int kk = 0; kk < 4; ++kk)
                    mma_f16(c, Ar[mb][kk], bh[2 * kk], bh[2 * kk + 1]);
            }
        }
    }

    // epilogue
    float* P = part_buf_dev
             + ((size_t)blockIdx.y * NN + row0 + rw * 32) * D + cw * (D / 2);
    const int r0 = lane >> 2;
    const int c0 = (lane & 3) * 2;
    #pragma unroll
    for (int mb = 0; mb < 2; ++mb)
        #pragma unroll
        for (int j = 0; j < NJ; ++j) {
            float* c = acc[mb][j];
            *(float2*)&P[(size_t)(mb * 16 + r0) * D + j * 8 + c0]     = make_float2(c[0], c[1]);
            *(float2*)&P[(size_t)(mb * 16 + r0 + 8) * D + j * 8 + c0] = make_float2(c[2], c[3]);
        }
}

// ---------------------------------------------------------------------------
// Row-wise: h = relu?(inv_prev * sum partials) ; g = h @ W^T
//   writes G^T fp32 (coalesced per (j, warp)) + per-layer max|g|
// ---------------------------------------------------------------------------
template<int DIN, int DOUT, int KS, bool RELU, int LAYER, int PREV>
__global__ void __launch_bounds__(256)
row_gemm(const float* __restrict__ xsrc, const float* __restrict__ W) {
    __shared__ float Ws[DOUT * DIN];
    for (int i = threadIdx.x; i < DOUT * DIN; i += 256) Ws[i] = W[i];
    __syncthreads();

    const float inv = (PREV >= 0) ? (1.0f / scale_of(PREV)) : 1.0f;
    const float* __restrict__ src = (PREV >= 0) ? part_buf_dev : xsrc;
    const int r = blockIdx.x * 256 + threadIdx.x;

    float h[DIN];
    #pragma unroll
    for (int i4 = 0; i4 < DIN / 4; ++i4) {
        float4 v = *(const float4*)(src + (size_t)r * DIN + i4 * 4);
        h[4 * i4 + 0] = v.x; h[4 * i4 + 1] = v.y;
        h[4 * i4 + 2] = v.z; h[4 * i4 + 3] = v.w;
    }
    #pragma unroll
    for (int s = 1; s < KS; ++s)
        #pragma unroll
        for (int i4 = 0; i4 < DIN / 4; ++i4) {
            float4 v = *(const float4*)(src + ((size_t)s * NN + r) * DIN + i4 * 4);
            h[4 * i4 + 0] += v.x; h[4 * i4 + 1] += v.y;
            h[4 * i4 + 2] += v.z; h[4 * i4 + 3] += v.w;
        }
    #pragma unroll
    for (int i = 0; i < DIN; ++i) {
        h[i] *= inv;
        if (RELU) h[i] = fmaxf(h[i], 0.0f);
    }

    float m = 0.0f;
    #pragma unroll
    for (int j = 0; j < DOUT; ++j) {
        float a = 0.0f;
        const float* w = &Ws[j * DIN];
        #pragma unroll
        for (int i = 0; i < DIN; ++i) a = fmaf(h[i], w[i], a);
        gt32_dev[(size_t)j * NN + r] = a;      // transposed, coalesced per j
        m = fmaxf(m, fabsf(a));
    }
    #pragma unroll
    for (int o = 16; o; o >>= 1)
        m = fmaxf(m, __shfl_xor_sync(0xFFFFFFFFu, m, o));
    if ((threadIdx.x & 31) == 0)
        atomicMax(&g_max_dev[LAYER], __float_as_uint(m));
}

// ---------------------------------------------------------------------------
// Convert: G^T fp32 -> scaled fp16 (hi only); fully coalesced both sides
// ---------------------------------------------------------------------------
__global__ void __launch_bounds__(256)
convert_g(int L) {
    const size_t i = (size_t)blockIdx.x * 256 + threadIdx.x;
    const float s = scale_of(L);
    gt_h_dev[i] = __float2half_rn(gt32_dev[i] * s);
}

// ---------------------------------------------------------------------------
// Final reduce: out = inv_s4 * sum of KSPLIT partials
// ---------------------------------------------------------------------------
__global__ void __launch_bounds__(256)
reduce_out(float* __restrict__ out) {
    const int idx = blockIdx.x * 256 + threadIdx.x;   // float4 index
    const float4* p4 = (const float4*)part_buf_dev;
    float4 a = p4[idx];
    #pragma unroll
    for (int s = 1; s < KSPLIT; ++s) {
        float4 b = p4[(size_t)s * (NN * 32 / 4) + idx];
        a.x += b.x; a.y += b.y; a.z += b.z; a.w += b.w;
    }
    const float inv = 1.0f / scale_of(3);
    a.x *= inv; a.y *= inv; a.z *= inv; a.w *= inv;
    ((float4*)out)[idx] = a;
}

// ---------------------------------------------------------------------------
// Launch
// ---------------------------------------------------------------------------
extern "C" void kernel_launch(void* const* d_in, const int* in_sizes, int n_in,
                              void* d_out, int out_size) {
    (void)in_sizes; (void)n_in; (void)out_size;
    const float* A  = (const float*)d_in[0];
    const float* X  = (const float*)d_in[1];
    const float* W1 = (const float*)d_in[2];
    const float* W2 = (const float*)d_in[3];
    const float* W3 = (const float*)d_in[4];
    const float* W4 = (const float*)d_in[5];
    float* out = (float*)d_out;

    constexpr int SM32 = 4 * (16384 + 32 * 128);   // 81920
    constexpr int SM64 = 4 * (16384 + 64 * 128);   // 98304
    cudaFuncSetAttribute(big_mma<32>, cudaFuncAttributeMaxDynamicSharedMemorySize, SM32);
    cudaFuncSetAttribute(big_mma<64>, cudaFuncAttributeMaxDynamicSharedMemorySize, SM64);

    const dim3 big_grid(NN / 128, KSPLIT);   // 64 x 4 = 256 CTAs (single wave)

    split_a<<<NN * NN / 8 / 256, 256>>>(A);

    // Layer 1
    row_gemm<32, 32, 1, false, 0, -1><<<NN / 256, 256>>>(X, W1);
    convert_g<<<NN * 32 / 256, 256>>>(0);
    big_mma<32><<<big_grid, 256, SM32>>>();
    // Layer 2
    row_gemm<32, 64, KSPLIT, true, 1, 0><<<NN / 256, 256>>>(nullptr, W2);
    convert_g<<<NN * 64 / 256, 256>>>(1);
    big_mma<64><<<big_grid, 256, SM64>>>();
    // Layer 3
    row_gemm<64, 64, KSPLIT, true, 2, 1><<<NN / 256, 256>>>(nullptr, W3);
    convert_g<<<NN * 64 / 256, 256>>>(2);
    big_mma<64><<<big_grid, 256, SM64>>>();
    // Layer 4 (relu applies to h3; output layer has no relu afterwards)
    row_gemm<64, 32, KSPLIT, true, 3, 2><<<NN / 256, 256>>>(nullptr, W4);
    convert_g<<<NN * 32 / 256, 256>>>(3);
    big_mma<32><<<big_grid, 256, SM32>>>();

    reduce_out<<<NN * 32 / 4 / 256, 256>>>(out);
}

// round 11
// speedup vs baseline: 2.0520x; 1.0726x over previous
#include <cuda_runtime.h>
#include <cuda_fp16.h>
#include <cstdint>

#define NN 8192
#define KSPLIT 4
#define KCH (NN / KSPLIT)          // 2048
#define BK 64
#define NTILES (KCH / BK)          // 32
#define KSPLIT1 2                  // layer-1 fused kernel (1 CTA/SM)
#define KCH1 (NN / KSPLIT1)        // 4096
#define NTILES1 (KCH1 / BK)        // 64

// ---------------------------------------------------------------------------
// Scratch (no cudaMalloc allowed)
// ---------------------------------------------------------------------------
__device__ __half a16_dev[(size_t)NN * NN];           // A in fp16 (128 MB)
__device__ __half gt_h_dev[64 * NN];                  // G^T hi [D][NN], scaled
__device__ float  gt32_dev[64 * NN];                  // G^T fp32 (true scale)
__device__ float  part_buf_dev[(size_t)KSPLIT * NN * 64];  // split-K partials
__device__ unsigned g_max_dev[4];                     // monotone across replays

// ---------------------------------------------------------------------------
// PTX helpers (plain sm_103-legal)
// ---------------------------------------------------------------------------
__device__ __forceinline__ uint32_t smem_u32(const void* p) {
    uint32_t a;
    asm("{ .reg .u64 t; cvta.to.shared.u64 t, %1; cvt.u32.u64 %0, t; }"
        : "=r"(a) : "l"(p));
    return a;
}
__device__ __forceinline__ void cp16(uint32_t dst, const void* src) {
    asm volatile("cp.async.cg.shared.global [%0], [%1], 16;\n"
                 :: "r"(dst), "l"(src));
}
#define CP_COMMIT() asm volatile("cp.async.commit_group;" ::: "memory")
#define CP_WAIT0()  asm volatile("cp.async.wait_group 0;" ::: "memory")
#define CP_WAIT1()  asm volatile("cp.async.wait_group 1;" ::: "memory")
#define CP_WAIT2()  asm volatile("cp.async.wait_group 2;" ::: "memory")
#define SWZ128(x) ((x) ^ (((x) >> 3) & 0x70))

__device__ __forceinline__ void ldm4(uint32_t* a, uint32_t addr) {
    asm volatile("ldmatrix.sync.aligned.m8n8.x4.shared.b16 {%0,%1,%2,%3}, [%4];"
                 : "=r"(a[0]), "=r"(a[1]), "=r"(a[2]), "=r"(a[3]) : "r"(addr));
}
__device__ __forceinline__ void mma_f16(float* c, const uint32_t* a,
                                        uint32_t b0, uint32_t b1) {
    asm volatile(
        "mma.sync.aligned.m16n8k16.row.col.f32.f16.f16.f32 "
        "{%0,%1,%2,%3},{%4,%5,%6,%7},{%8,%9},{%0,%1,%2,%3};"
        : "+f"(c[0]), "+f"(c[1]), "+f"(c[2]), "+f"(c[3])
        : "r"(a[0]), "r"(a[1]), "r"(a[2]), "r"(a[3]), "r"(b0), "r"(b1));
}

// power-of-2 scale so max|g|*s <= 30000; identical math in every consumer
__device__ __forceinline__ float scale_of(int L) {
    float m = __uint_as_float(g_max_dev[L]);
    float s = 1.0f;
    if (m > 0.0f) s = exp2f(-ceilf(log2f(m / 30000.0f)));
    if (!(s > 0.0f) || isinf(s)) s = 1.0f;
    return s;
}

// ---------------------------------------------------------------------------
// Layer-1 fused kernel: converts A fp32 -> fp16 (writes a16_dev) AND computes
//   part[ks] = A @ G1.  BM=128, BK=64, 1 CTA/SM, 4 stages, distance 3.
//   Stage: A fp32 (32KB, linear) + A fp16 (16KB, swizzled) + G (4KB).
// ---------------------------------------------------------------------------
__global__ void __launch_bounds__(256, 1)
conv_mma(const float* __restrict__ A) {
    constexpr int D    = 32;
    constexpr int NJ   = D / 16;           // 2
    constexpr int GPL  = D * 128;          // 4096
    constexpr int A32B = 128 * 256;        // 32768 (fp32 plane)
    constexpr int A16B = 128 * 128;        // 16384 (fp16 plane)
    constexpr int STAGE = A32B + A16B + GPL;  // 53248

    extern __shared__ __align__(1024) char smem[];
    const uint32_t sb = smem_u32(smem);
    const int tid  = threadIdx.x;
    const int wid  = tid >> 5;
    const int lane = tid & 31;
    const int rw   = wid >> 1;             // row group 0..3
    const int cw   = wid & 1;              // col group 0..1
    const size_t row0 = (size_t)blockIdx.x * 128;
    const size_t k0   = (size_t)blockIdx.y * KCH1;

    auto load_tile = [&](int st, int kt) {
        const uint32_t base = sb + st * STAGE;
        const size_t   ke   = k0 + (size_t)kt * BK;
        #pragma unroll
        for (int p = 0; p < 8; ++p) {       // A fp32: 128 rows x 16 chunks
            const int c = p * 256 + tid;
            const int r = c >> 4, ch = c & 15;
            cp16(base + (uint32_t)(r * 256 + ch * 16),
                 A + (row0 + r) * NN + ke + ch * 4);
        }
        {                                   // G: 32 rows x 8 chunks
            const int r = tid >> 3, ch = tid & 7;
            cp16(base + A32B + A16B + SWZ128((uint32_t)(r * 128 + ch * 16)),
                 gt_h_dev + (size_t)r * NN + ke + ch * 8);
        }
    };

    float acc[2][NJ][4];
    #pragma unroll
    for (int mb = 0; mb < 2; ++mb)
        #pragma unroll
        for (int j = 0; j < NJ; ++j)
            #pragma unroll
            for (int q = 0; q < 4; ++q) acc[mb][j][q] = 0.0f;

    load_tile(0, 0); CP_COMMIT();
    load_tile(1, 1); CP_COMMIT();
    load_tile(2, 2); CP_COMMIT();

    for (int kt = 0; kt < NTILES1; ++kt) {
        if (kt < NTILES1 - 2)       CP_WAIT2();
        else if (kt == NTILES1 - 2) CP_WAIT1();
        else                        CP_WAIT0();
        __syncthreads();

        if (kt + 3 < NTILES1) { load_tile((kt + 3) & 3, kt + 3); CP_COMMIT(); }

        const int st = kt & 3;
        const uint32_t base = sb + st * STAGE;
        const size_t   ke   = k0 + (size_t)kt * BK;

        // convert: fp32 plane -> fp16 plane (STS) + a16_dev (STG)
        #pragma unroll
        for (int p = 0; p < 8; ++p) {
            const int c = p * 256 + tid;
            const int r = c >> 4, ch = c & 15;
            const float4 v = *(const float4*)(smem + st * STAGE + r * 256 + ch * 16);
            __half2 h01 = __floats2half2_rn(v.x, v.y);
            __half2 h23 = __floats2half2_rn(v.z, v.w);
            uint2 pk;
            pk.x = *reinterpret_cast<uint32_t*>(&h01);
            pk.y = *reinterpret_cast<uint32_t*>(&h23);
            *(uint2*)(a16_dev + (row0 + r) * NN + ke + ch * 4) = pk;
            *(uint2*)(smem + st * STAGE + A32B
                      + SWZ128((uint32_t)(r * 128 + ch * 8))) = pk;
        }
        __syncthreads();                   // fp16 plane visible to all warps

        // MMA from fp16 plane (identical fragment geometry to big_mma)
        const uint32_t ab16 = base + A32B;
        uint32_t Ar[2][4][4];
        #pragma unroll
        for (int mb = 0; mb < 2; ++mb)
            #pragma unroll
            for (int kk = 0; kk < 4; ++kk)
                ldm4(Ar[mb][kk], ab16 + SWZ128((uint32_t)(
                    (rw * 32 + mb * 16 + (lane & 15)) * 128
                    + kk * 32 + (lane >> 4) * 16)));

        const uint32_t gb = base + A32B + A16B;
        #pragma unroll
        for (int j = 0; j < NJ; ++j) {
            const uint32_t nrow = (uint32_t)((cw * (D / 2) + j * 8 + (lane & 7)) * 128
                                             + (lane >> 3) * 16);
            uint32_t bh[8];
            ldm4(bh,     gb + SWZ128(nrow));
            ldm4(bh + 4, gb + SWZ128(nrow + 64));
            #pragma unroll
            for (int mb = 0; mb < 2; ++mb) {
                float* c = acc[mb][j];
                #pragma unroll
                for (int kk = 0; kk < 4; ++kk)
                    mma_f16(c, Ar[mb][kk], bh[2 * kk], bh[2 * kk + 1]);
            }
        }
    }

    float* P = part_buf_dev
             + ((size_t)blockIdx.y * NN + row0 + rw * 32) * D + cw * (D / 2);
    const int r0 = lane >> 2;
    const int c0 = (lane & 3) * 2;
    #pragma unroll
    for (int mb = 0; mb < 2; ++mb)
        #pragma unroll
        for (int j = 0; j < NJ; ++j) {
            float* c = acc[mb][j];
            *(float2*)&P[(size_t)(mb * 16 + r0) * D + j * 8 + c0]     = make_float2(c[0], c[1]);
            *(float2*)&P[(size_t)(mb * 16 + r0 + 8) * D + j * 8 + c0] = make_float2(c[2], c[3]);
        }
}

// ---------------------------------------------------------------------------
// Big GEMM (layers 2-4): part[ks] = A16 @ Gscaled_hi, 4 stages, distance 3.
// ---------------------------------------------------------------------------
template<int D>
__global__ void __launch_bounds__(256, 2)
big_mma() {
    constexpr int NJ    = D / 16;
    constexpr int GPL   = D * 128;
    constexpr int ATB   = 128 * 128;
    constexpr int STAGE = ATB + GPL;
    constexpr int GCHK  = D * 8;

    extern __shared__ __align__(1024) char smem[];
    const uint32_t sb = smem_u32(smem);
    const int tid  = threadIdx.x;
    const int wid  = tid >> 5;
    const int lane = tid & 31;
    const int rw   = wid >> 1;
    const int cw   = wid & 1;
    const size_t row0 = (size_t)blockIdx.x * 128;
    const size_t k0   = (size_t)blockIdx.y * KCH;

    auto load_tile = [&](int st, int kt) {
        const uint32_t base = sb + st * STAGE;
        const size_t   ke   = k0 + (size_t)kt * BK;
        #pragma unroll
        for (int p = 0; p < 4; ++p) {
            const int c = p * 256 + tid;
            const int r = c >> 3, ch = c & 7;
            cp16(base + SWZ128((uint32_t)(r * 128 + ch * 16)),
                 a16_dev + (row0 + r) * NN + ke + ch * 8);
        }
        #pragma unroll
        for (int p = 0; p < GCHK / 256; ++p) {
            const int c = p * 256 + tid;
            const int r = c >> 3, ch = c & 7;
            cp16(base + ATB + SWZ128((uint32_t)(r * 128 + ch * 16)),
                 gt_h_dev + (size_t)r * NN + ke + ch * 8);
        }
    };

    float acc[2][NJ][4];
    #pragma unroll
    for (int mb = 0; mb < 2; ++mb)
        #pragma unroll
        for (int j = 0; j < NJ; ++j)
            #pragma unroll
            for (int q = 0; q < 4; ++q) acc[mb][j][q] = 0.0f;

    load_tile(0, 0); CP_COMMIT();
    load_tile(1, 1); CP_COMMIT();
    load_tile(2, 2); CP_COMMIT();

    for (int kt = 0; kt < NTILES; ++kt) {
        if (kt < NTILES - 2)       CP_WAIT2();
        else if (kt == NTILES - 2) CP_WAIT1();
        else                       CP_WAIT0();
        __syncthreads();

        if (kt + 3 < NTILES) { load_tile((kt + 3) & 3, kt + 3); CP_COMMIT(); }

        const uint32_t base = sb + (kt & 3) * STAGE;

        uint32_t Ar[2][4][4];
        #pragma unroll
        for (int mb = 0; mb < 2; ++mb)
            #pragma unroll
            for (int kk = 0; kk < 4; ++kk)
                ldm4(Ar[mb][kk], base + SWZ128((uint32_t)(
                    (rw * 32 + mb * 16 + (lane & 15)) * 128
                    + kk * 32 + (lane >> 4) * 16)));

        const uint32_t gb = base + ATB;
        #pragma unroll
        for (int j = 0; j < NJ; ++j) {
            const uint32_t nrow = (uint32_t)((cw * (D / 2) + j * 8 + (lane & 7)) * 128
                                             + (lane >> 3) * 16);
            uint32_t bh[8];
            ldm4(bh,     gb + SWZ128(nrow));
            ldm4(bh + 4, gb + SWZ128(nrow + 64));
            #pragma unroll
            for (int mb = 0; mb < 2; ++mb) {
                float* c = acc[mb][j];
                #pragma unroll
                for (int kk = 0; kk < 4; ++kk)
                    mma_f16(c, Ar[mb][kk], bh[2 * kk], bh[2 * kk + 1]);
            }
        }
    }

    float* P = part_buf_dev
             + ((size_t)blockIdx.y * NN + row0 + rw * 32) * D + cw * (D / 2);
    const int r0 = lane >> 2;
    const int c0 = (lane & 3) * 2;
    #pragma unroll
    for (int mb = 0; mb < 2; ++mb)
        #pragma unroll
        for (int j = 0; j < NJ; ++j) {
            float* c = acc[mb][j];
            *(float2*)&P[(size_t)(mb * 16 + r0) * D + j * 8 + c0]     = make_float2(c[0], c[1]);
            *(float2*)&P[(size_t)(mb * 16 + r0 + 8) * D + j * 8 + c0] = make_float2(c[2], c[3]);
        }
}

// ---------------------------------------------------------------------------
// Row-wise: h = relu?(inv_prev * sum partials) ; g = h @ W^T -> G^T fp32 + max
// ---------------------------------------------------------------------------
template<int DIN, int DOUT, int KS, bool RELU, int LAYER, int PREV>
__global__ void __launch_bounds__(256)
row_gemm(const float* __restrict__ xsrc, const float* __restrict__ W) {
    __shared__ float Ws[DOUT * DIN];
    for (int i = threadIdx.x; i < DOUT * DIN; i += 256) Ws[i] = W[i];
    __syncthreads();

    const float inv = (PREV >= 0) ? (1.0f / scale_of(PREV)) : 1.0f;
    const float* __restrict__ src = (PREV >= 0) ? part_buf_dev : xsrc;
    const int r = blockIdx.x * 256 + threadIdx.x;

    float h[DIN];
    #pragma unroll
    for (int i4 = 0; i4 < DIN / 4; ++i4) {
        float4 v = *(const float4*)(src + (size_t)r * DIN + i4 * 4);
        h[4 * i4 + 0] = v.x; h[4 * i4 + 1] = v.y;
        h[4 * i4 + 2] = v.z; h[4 * i4 + 3] = v.w;
    }
    #pragma unroll
    for (int s = 1; s < KS; ++s)
        #pragma unroll
        for (int i4 = 0; i4 < DIN / 4; ++i4) {
            float4 v = *(const float4*)(src + ((size_t)s * NN + r) * DIN + i4 * 4);
            h[4 * i4 + 0] += v.x; h[4 * i4 + 1] += v.y;
            h[4 * i4 + 2] += v.z; h[4 * i4 + 3] += v.w;
        }
    #pragma unroll
    for (int i = 0; i < DIN; ++i) {
        h[i] *= inv;
        if (RELU) h[i] = fmaxf(h[i], 0.0f);
    }

    float m = 0.0f;
    #pragma unroll
    for (int j = 0; j < DOUT; ++j) {
        float a = 0.0f;
        const float* w = &Ws[j * DIN];
        #pragma unroll
        for (int i = 0; i < DIN; ++i) a = fmaf(h[i], w[i], a);
        gt32_dev[(size_t)j * NN + r] = a;
        m = fmaxf(m, fabsf(a));
    }
    #pragma unroll
    for (int o = 16; o; o >>= 1)
        m = fmaxf(m, __shfl_xor_sync(0xFFFFFFFFu, m, o));
    if ((threadIdx.x & 31) == 0)
        atomicMax(&g_max_dev[LAYER], __float_as_uint(m));
    // no reset needed: atomicMax over identical data is idempotent per replay
}

// ---------------------------------------------------------------------------
// Convert: G^T fp32 -> scaled fp16; fully coalesced
// ---------------------------------------------------------------------------
__global__ void __launch_bounds__(256)
convert_g(int L) {
    const size_t i = (size_t)blockIdx.x * 256 + threadIdx.x;
    const float s = scale_of(L);
    gt_h_dev[i] = __float2half_rn(gt32_dev[i] * s);
}

// ---------------------------------------------------------------------------
// Final reduce: out = inv_s4 * sum of KSPLIT partials
// ---------------------------------------------------------------------------
__global__ void __launch_bounds__(256)
reduce_out(float* __restrict__ out) {
    const int idx = blockIdx.x * 256 + threadIdx.x;
    const float4* p4 = (const float4*)part_buf_dev;
    float4 a = p4[idx];
    #pragma unroll
    for (int s = 1; s < KSPLIT; ++s) {
        float4 b = p4[(size_t)s * (NN * 32 / 4) + idx];
        a.x += b.x; a.y += b.y; a.z += b.z; a.w += b.w;
    }
    const float inv = 1.0f / scale_of(3);
    a.x *= inv; a.y *= inv; a.z *= inv; a.w *= inv;
    ((float4*)out)[idx] = a;
}

// ---------------------------------------------------------------------------
// Launch
// ---------------------------------------------------------------------------
extern "C" void kernel_launch(void* const* d_in, const int* in_sizes, int n_in,
                              void* d_out, int out_size) {
    (void)in_sizes; (void)n_in; (void)out_size;
    const float* A  = (const float*)d_in[0];
    const float* X  = (const float*)d_in[1];
    const float* W1 = (const float*)d_in[2];
    const float* W2 = (const float*)d_in[3];
    const float* W3 = (const float*)d_in[4];
    const float* W4 = (const float*)d_in[5];
    float* out = (float*)d_out;

    constexpr int SMC  = 4 * (32768 + 16384 + 32 * 128);   // 212992
    constexpr int SM32 = 4 * (16384 + 32 * 128);           // 81920
    constexpr int SM64 = 4 * (16384 + 64 * 128);           // 98304
    cudaFuncSetAttribute(conv_mma,    cudaFuncAttributeMaxDynamicSharedMemorySize, SMC);
    cudaFuncSetAttribute(big_mma<32>, cudaFuncAttributeMaxDynamicSharedMemorySize, SM32);
    cudaFuncSetAttribute(big_mma<64>, cudaFuncAttributeMaxDynamicSharedMemorySize, SM64);

    const dim3 big_grid(NN / 128, KSPLIT);     // 256 CTAs (single wave @2/SM)
    const dim3 conv_grid(NN / 128, KSPLIT1);   // 128 CTAs (single wave @1/SM)

    // Layer 1: G1 = X @ W1^T ; fused A-convert + P = A @ G1
    row_gemm<32, 32, 1, false, 0, -1><<<NN / 256, 256>>>(X, W1);
    convert_g<<<NN * 32 / 256, 256>>>(0);
    conv_mma<<<conv_grid, 256, SMC>>>(A);
    // Layer 2 (partials from layer 1 have KSPLIT1 splits)
    row_gemm<32, 64, KSPLIT1, true, 1, 0><<<NN / 256, 256>>>(nullptr, W2);
    convert_g<<<NN * 64 / 256, 256>>>(1);
    big_mma<64><<<big_grid, 256, SM64>>>();
    // Layer 3
    row_gemm<64, 64, KSPLIT, true, 2, 1><<<NN / 256, 256>>>(nullptr, W3);
    convert_g<<<NN * 64 / 256, 256>>>(2);
    big_mma<64><<<big_grid, 256, SM64>>>();
    // Layer 4
    row_gemm<64, 32, KSPLIT, true, 3, 2><<<NN / 256, 256>>>(nullptr, W4);
    convert_g<<<NN * 32 / 256, 256>>>(3);
    big_mma<32><<<big_grid, 256, SM32>>>();

    reduce_out<<<NN * 32 / 4 / 256, 256>>>(out);
}

// round 12
// speedup vs baseline: 2.1119x; 1.0292x over previous
#include <cuda_runtime.h>
#include <cuda_fp16.h>
#include <cstdint>

#define NN 8192
#define KSPLIT 4
#define KCH (NN / KSPLIT)          // 2048
#define BK 64
#define NTILES (KCH / BK)          // 32
#define KSPLIT1 2                  // layer-1 fused kernel (1 CTA/SM)
#define KCH1 (NN / KSPLIT1)        // 4096
#define NTILES1 (KCH1 / BK)        // 64

// ---------------------------------------------------------------------------
// Scratch (no cudaMalloc allowed)
// ---------------------------------------------------------------------------
__device__ __half a16_dev[(size_t)NN * NN];           // A in fp16 (128 MB)
__device__ __half gt_h_dev[64 * NN];                  // G^T hi [D][NN], scaled
__device__ float  gt32_dev[64 * NN];                  // G^T fp32 (true scale)
__device__ float  part_buf_dev[(size_t)KSPLIT * NN * 64];  // split-K partials
__device__ unsigned g_max_dev[4];                     // monotone across replays

// ---------------------------------------------------------------------------
// PTX helpers (plain sm_103-legal)
// ---------------------------------------------------------------------------
__device__ __forceinline__ uint32_t smem_u32(const void* p) {
    uint32_t a;
    asm("{ .reg .u64 t; cvta.to.shared.u64 t, %1; cvt.u32.u64 %0, t; }"
        : "=r"(a) : "l"(p));
    return a;
}
__device__ __forceinline__ void cp16(uint32_t dst, const void* src) {
    asm volatile("cp.async.cg.shared.global [%0], [%1], 16;\n"
                 :: "r"(dst), "l"(src));
}
#define CP_COMMIT() asm volatile("cp.async.commit_group;" ::: "memory")
#define CP_WAIT0()  asm volatile("cp.async.wait_group 0;" ::: "memory")
#define CP_WAIT1()  asm volatile("cp.async.wait_group 1;" ::: "memory")
#define CP_WAIT2()  asm volatile("cp.async.wait_group 2;" ::: "memory")
#define SWZ128(x) ((x) ^ (((x) >> 3) & 0x70))

__device__ __forceinline__ void ldm4(uint32_t* a, uint32_t addr) {
    asm volatile("ldmatrix.sync.aligned.m8n8.x4.shared.b16 {%0,%1,%2,%3}, [%4];"
                 : "=r"(a[0]), "=r"(a[1]), "=r"(a[2]), "=r"(a[3]) : "r"(addr));
}
__device__ __forceinline__ void mma_f16(float* c, const uint32_t* a,
                                        uint32_t b0, uint32_t b1) {
    asm volatile(
        "mma.sync.aligned.m16n8k16.row.col.f32.f16.f16.f32 "
        "{%0,%1,%2,%3},{%4,%5,%6,%7},{%8,%9},{%0,%1,%2,%3};"
        : "+f"(c[0]), "+f"(c[1]), "+f"(c[2]), "+f"(c[3])
        : "r"(a[0]), "r"(a[1]), "r"(a[2]), "r"(a[3]), "r"(b0), "r"(b1));
}

// power-of-2 scale so max|g|*s <= 30000; identical math in every consumer
__device__ __forceinline__ float scale_of(int L) {
    float m = __uint_as_float(g_max_dev[L]);
    float s = 1.0f;
    if (m > 0.0f) s = exp2f(-ceilf(log2f(m / 30000.0f)));
    if (!(s > 0.0f) || isinf(s)) s = 1.0f;
    return s;
}

// ---------------------------------------------------------------------------
// Layer-1 fused kernel: converts A fp32 -> fp16 (writes a16_dev) AND computes
//   part[ks] = A @ G1.  BM=128, BK=64, 1 CTA/SM, 4 stages, distance 3.
// ---------------------------------------------------------------------------
__global__ void __launch_bounds__(256, 1)
conv_mma(const float* __restrict__ A) {
    constexpr int D    = 32;
    constexpr int NJ   = D / 16;           // 2
    constexpr int GPL  = D * 128;          // 4096
    constexpr int A32B = 128 * 256;        // 32768 (fp32 plane)
    constexpr int A16B = 128 * 128;        // 16384 (fp16 plane)
    constexpr int STAGE = A32B + A16B + GPL;  // 53248

    extern __shared__ __align__(1024) char smem[];
    const uint32_t sb = smem_u32(smem);
    const int tid  = threadIdx.x;
    const int wid  = tid >> 5;
    const int lane = tid & 31;
    const int rw   = wid >> 1;
    const int cw   = wid & 1;
    const size_t row0 = (size_t)blockIdx.x * 128;
    const size_t k0   = (size_t)blockIdx.y * KCH1;

    auto load_tile = [&](int st, int kt) {
        const uint32_t base = sb + st * STAGE;
        const size_t   ke   = k0 + (size_t)kt * BK;
        #pragma unroll
        for (int p = 0; p < 8; ++p) {
            const int c = p * 256 + tid;
            const int r = c >> 4, ch = c & 15;
            cp16(base + (uint32_t)(r * 256 + ch * 16),
                 A + (row0 + r) * NN + ke + ch * 4);
        }
        {
            const int r = tid >> 3, ch = tid & 7;
            cp16(base + A32B + A16B + SWZ128((uint32_t)(r * 128 + ch * 16)),
                 gt_h_dev + (size_t)r * NN + ke + ch * 8);
        }
    };

    float acc[2][NJ][4];
    #pragma unroll
    for (int mb = 0; mb < 2; ++mb)
        #pragma unroll
        for (int j = 0; j < NJ; ++j)
            #pragma unroll
            for (int q = 0; q < 4; ++q) acc[mb][j][q] = 0.0f;

    load_tile(0, 0); CP_COMMIT();
    load_tile(1, 1); CP_COMMIT();
    load_tile(2, 2); CP_COMMIT();

    for (int kt = 0; kt < NTILES1; ++kt) {
        if (kt < NTILES1 - 2)       CP_WAIT2();
        else if (kt == NTILES1 - 2) CP_WAIT1();
        else                        CP_WAIT0();
        __syncthreads();

        if (kt + 3 < NTILES1) { load_tile((kt + 3) & 3, kt + 3); CP_COMMIT(); }

        const int st = kt & 3;
        const uint32_t base = sb + st * STAGE;
        const size_t   ke   = k0 + (size_t)kt * BK;

        #pragma unroll
        for (int p = 0; p < 8; ++p) {
            const int c = p * 256 + tid;
            const int r = c >> 4, ch = c & 15;
            const float4 v = *(const float4*)(smem + st * STAGE + r * 256 + ch * 16);
            __half2 h01 = __floats2half2_rn(v.x, v.y);
            __half2 h23 = __floats2half2_rn(v.z, v.w);
            uint2 pk;
            pk.x = *reinterpret_cast<uint32_t*>(&h01);
            pk.y = *reinterpret_cast<uint32_t*>(&h23);
            *(uint2*)(a16_dev + (row0 + r) * NN + ke + ch * 4) = pk;
            *(uint2*)(smem + st * STAGE + A32B
                      + SWZ128((uint32_t)(r * 128 + ch * 8))) = pk;
        }
        __syncthreads();

        const uint32_t ab16 = base + A32B;
        uint32_t Ar[2][4][4];
        #pragma unroll
        for (int mb = 0; mb < 2; ++mb)
            #pragma unroll
            for (int kk = 0; kk < 4; ++kk)
                ldm4(Ar[mb][kk], ab16 + SWZ128((uint32_t)(
                    (rw * 32 + mb * 16 + (lane & 15)) * 128
                    + kk * 32 + (lane >> 4) * 16)));

        const uint32_t gb = base + A32B + A16B;
        #pragma unroll
        for (int j = 0; j < NJ; ++j) {
            const uint32_t nrow = (uint32_t)((cw * (D / 2) + j * 8 + (lane & 7)) * 128
                                             + (lane >> 3) * 16);
            uint32_t bh[8];
            ldm4(bh,     gb + SWZ128(nrow));
            ldm4(bh + 4, gb + SWZ128(nrow + 64));
            #pragma unroll
            for (int mb = 0; mb < 2; ++mb) {
                float* c = acc[mb][j];
                #pragma unroll
                for (int kk = 0; kk < 4; ++kk)
                    mma_f16(c, Ar[mb][kk], bh[2 * kk], bh[2 * kk + 1]);
            }
        }
    }

    float* P = part_buf_dev
             + ((size_t)blockIdx.y * NN + row0 + rw * 32) * D + cw * (D / 2);
    const int r0 = lane >> 2;
    const int c0 = (lane & 3) * 2;
    #pragma unroll
    for (int mb = 0; mb < 2; ++mb)
        #pragma unroll
        for (int j = 0; j < NJ; ++j) {
            float* c = acc[mb][j];
            *(float2*)&P[(size_t)(mb * 16 + r0) * D + j * 8 + c0]     = make_float2(c[0], c[1]);
            *(float2*)&P[(size_t)(mb * 16 + r0 + 8) * D + j * 8 + c0] = make_float2(c[2], c[3]);
        }
}

// ---------------------------------------------------------------------------
// Big GEMM (layers 2-4): part[ks] = A16 @ Gscaled_hi, 4 stages, distance 3.
// ---------------------------------------------------------------------------
template<int D>
__global__ void __launch_bounds__(256, 2)
big_mma() {
    constexpr int NJ    = D / 16;
    constexpr int GPL   = D * 128;
    constexpr int ATB   = 128 * 128;
    constexpr int STAGE = ATB + GPL;
    constexpr int GCHK  = D * 8;

    extern __shared__ __align__(1024) char smem[];
    const uint32_t sb = smem_u32(smem);
    const int tid  = threadIdx.x;
    const int wid  = tid >> 5;
    const int lane = tid & 31;
    const int rw   = wid >> 1;
    const int cw   = wid & 1;
    const size_t row0 = (size_t)blockIdx.x * 128;
    const size_t k0   = (size_t)blockIdx.y * KCH;

    auto load_tile = [&](int st, int kt) {
        const uint32_t base = sb + st * STAGE;
        const size_t   ke   = k0 + (size_t)kt * BK;
        #pragma unroll
        for (int p = 0; p < 4; ++p) {
            const int c = p * 256 + tid;
            const int r = c >> 3, ch = c & 7;
            cp16(base + SWZ128((uint32_t)(r * 128 + ch * 16)),
                 a16_dev + (row0 + r) * NN + ke + ch * 8);
        }
        #pragma unroll
        for (int p = 0; p < GCHK / 256; ++p) {
            const int c = p * 256 + tid;
            const int r = c >> 3, ch = c & 7;
            cp16(base + ATB + SWZ128((uint32_t)(r * 128 + ch * 16)),
                 gt_h_dev + (size_t)r * NN + ke + ch * 8);
        }
    };

    float acc[2][NJ][4];
    #pragma unroll
    for (int mb = 0; mb < 2; ++mb)
        #pragma unroll
        for (int j = 0; j < NJ; ++j)
            #pragma unroll
            for (int q = 0; q < 4; ++q) acc[mb][j][q] = 0.0f;

    load_tile(0, 0); CP_COMMIT();
    load_tile(1, 1); CP_COMMIT();
    load_tile(2, 2); CP_COMMIT();

    for (int kt = 0; kt < NTILES; ++kt) {
        if (kt < NTILES - 2)       CP_WAIT2();
        else if (kt == NTILES - 2) CP_WAIT1();
        else                       CP_WAIT0();
        __syncthreads();

        if (kt + 3 < NTILES) { load_tile((kt + 3) & 3, kt + 3); CP_COMMIT(); }

        const uint32_t base = sb + (kt & 3) * STAGE;

        uint32_t Ar[2][4][4];
        #pragma unroll
        for (int mb = 0; mb < 2; ++mb)
            #pragma unroll
            for (int kk = 0; kk < 4; ++kk)
                ldm4(Ar[mb][kk], base + SWZ128((uint32_t)(
                    (rw * 32 + mb * 16 + (lane & 15)) * 128
                    + kk * 32 + (lane >> 4) * 16)));

        const uint32_t gb = base + ATB;
        #pragma unroll
        for (int j = 0; j < NJ; ++j) {
            const uint32_t nrow = (uint32_t)((cw * (D / 2) + j * 8 + (lane & 7)) * 128
                                             + (lane >> 3) * 16);
            uint32_t bh[8];
            ldm4(bh,     gb + SWZ128(nrow));
            ldm4(bh + 4, gb + SWZ128(nrow + 64));
            #pragma unroll
            for (int mb = 0; mb < 2; ++mb) {
                float* c = acc[mb][j];
                #pragma unroll
                for (int kk = 0; kk < 4; ++kk)
                    mma_f16(c, Ar[mb][kk], bh[2 * kk], bh[2 * kk + 1]);
            }
        }
    }

    float* P = part_buf_dev
             + ((size_t)blockIdx.y * NN + row0 + rw * 32) * D + cw * (D / 2);
    const int r0 = lane >> 2;
    const int c0 = (lane & 3) * 2;
    #pragma unroll
    for (int mb = 0; mb < 2; ++mb)
        #pragma unroll
        for (int j = 0; j < NJ; ++j) {
            float* c = acc[mb][j];
            *(float2*)&P[(size_t)(mb * 16 + r0) * D + j * 8 + c0]     = make_float2(c[0], c[1]);
            *(float2*)&P[(size_t)(mb * 16 + r0 + 8) * D + j * 8 + c0] = make_float2(c[2], c[3]);
        }
}

// ---------------------------------------------------------------------------
// Row-wise: 4 threads per row (q = tid&3 computes DOUT/4 outputs).
//   h = relu?(inv_prev * sum partials) ; g = h @ W^T -> G^T fp32 + max|g|
//   64 rows per 256-thread block -> grid 128.
// ---------------------------------------------------------------------------
template<int DIN, int DOUT, int KS, bool RELU, int LAYER, int PREV>
__global__ void __launch_bounds__(256)
row_gemm(const float* __restrict__ xsrc, const float* __restrict__ W) {
    constexpr int JQ = DOUT / 4;           // outputs per thread
    __shared__ float Ws[DOUT * DIN];
    for (int i = threadIdx.x; i < DOUT * DIN; i += 256) Ws[i] = W[i];
    __syncthreads();

    const float inv = (PREV >= 0) ? (1.0f / scale_of(PREV)) : 1.0f;
    const float* __restrict__ src = (PREV >= 0) ? part_buf_dev : xsrc;
    const int q = threadIdx.x & 3;         // output quarter
    const int r = blockIdx.x * 64 + (threadIdx.x >> 2);

    float h[DIN];
    #pragma unroll
    for (int i4 = 0; i4 < DIN / 4; ++i4) {
        float4 v = *(const float4*)(src + (size_t)r * DIN + i4 * 4);
        h[4 * i4 + 0] = v.x; h[4 * i4 + 1] = v.y;
        h[4 * i4 + 2] = v.z; h[4 * i4 + 3] = v.w;
    }
    #pragma unroll
    for (int s = 1; s < KS; ++s)
        #pragma unroll
        for (int i4 = 0; i4 < DIN / 4; ++i4) {
            float4 v = *(const float4*)(src + ((size_t)s * NN + r) * DIN + i4 * 4);
            h[4 * i4 + 0] += v.x; h[4 * i4 + 1] += v.y;
            h[4 * i4 + 2] += v.z; h[4 * i4 + 3] += v.w;
        }
    #pragma unroll
    for (int i = 0; i < DIN; ++i) {
        h[i] *= inv;
        if (RELU) h[i] = fmaxf(h[i], 0.0f);
    }

    float m = 0.0f;
    #pragma unroll
    for (int jj = 0; jj < JQ; ++jj) {
        const int j = q * JQ + jj;
        float a = 0.0f;
        const float* w = &Ws[j * DIN];
        #pragma unroll
        for (int i = 0; i < DIN; ++i) a = fmaf(h[i], w[i], a);
        gt32_dev[(size_t)j * NN + r] = a;
        m = fmaxf(m, fabsf(a));
    }
    #pragma unroll
    for (int o = 16; o; o >>= 1)
        m = fmaxf(m, __shfl_xor_sync(0xFFFFFFFFu, m, o));
    if ((threadIdx.x & 31) == 0)
        atomicMax(&g_max_dev[LAYER], __float_as_uint(m));
}

// ---------------------------------------------------------------------------
// Convert: G^T fp32 -> scaled fp16; fully coalesced
// ---------------------------------------------------------------------------
__global__ void __launch_bounds__(256)
convert_g(int L) {
    const size_t i = (size_t)blockIdx.x * 256 + threadIdx.x;
    const float s = scale_of(L);
    gt_h_dev[i] = __float2half_rn(gt32_dev[i] * s);
}

// ---------------------------------------------------------------------------
// Final reduce: out = inv_s4 * sum of KSPLIT partials
// ---------------------------------------------------------------------------
__global__ void __launch_bounds__(256)
reduce_out(float* __restrict__ out) {
    const int idx = blockIdx.x * 256 + threadIdx.x;
    const float4* p4 = (const float4*)part_buf_dev;
    float4 a = p4[idx];
    #pragma unroll
    for (int s = 1; s < KSPLIT; ++s) {
        float4 b = p4[(size_t)s * (NN * 32 / 4) + idx];
        a.x += b.x; a.y += b.y; a.z += b.z; a.w += b.w;
    }
    const float inv = 1.0f / scale_of(3);
    a.x *= inv; a.y *= inv; a.z *= inv; a.w *= inv;
    ((float4*)out)[idx] = a;
}

// ---------------------------------------------------------------------------
// Launch
// ---------------------------------------------------------------------------
extern "C" void kernel_launch(void* const* d_in, const int* in_sizes, int n_in,
                              void* d_out, int out_size) {
    (void)in_sizes; (void)n_in; (void)out_size;
    const float* A  = (const float*)d_in[0];
    const float* X  = (const float*)d_in[1];
    const float* W1 = (const float*)d_in[2];
    const float* W2 = (const float*)d_in[3];
    const float* W3 = (const float*)d_in[4];
    const float* W4 = (const float*)d_in[5];
    float* out = (float*)d_out;

    constexpr int SMC  = 4 * (32768 + 16384 + 32 * 128);   // 212992
    constexpr int SM32 = 4 * (16384 + 32 * 128);           // 81920
    constexpr int SM64 = 4 * (16384 + 64 * 128);           // 98304
    cudaFuncSetAttribute(conv_mma,    cudaFuncAttributeMaxDynamicSharedMemorySize, SMC);
    cudaFuncSetAttribute(big_mma<32>, cudaFuncAttributeMaxDynamicSharedMemorySize, SM32);
    cudaFuncSetAttribute(big_mma<64>, cudaFuncAttributeMaxDynamicSharedMemorySize, SM64);

    const dim3 big_grid(NN / 128, KSPLIT);     // 256 CTAs (single wave @2/SM)
    const dim3 conv_grid(NN / 128, KSPLIT1);   // 128 CTAs (single wave @1/SM)

    // Layer 1: G1 = X @ W1^T ; fused A-convert + P = A @ G1
    row_gemm<32, 32, 1, false, 0, -1><<<NN / 64, 256>>>(X, W1);
    convert_g<<<NN * 32 / 256, 256>>>(0);
    conv_mma<<<conv_grid, 256, SMC>>>(A);
    // Layer 2 (partials from layer 1 have KSPLIT1 splits)
    row_gemm<32, 64, KSPLIT1, true, 1, 0><<<NN / 64, 256>>>(nullptr, W2);
    convert_g<<<NN * 64 / 256, 256>>>(1);
    big_mma<64><<<big_grid, 256, SM64>>>();
    // Layer 3
    row_gemm<64, 64, KSPLIT, true, 2, 1><<<NN / 64, 256>>>(nullptr, W3);
    convert_g<<<NN * 64 / 256, 256>>>(2);
    big_mma<64><<<big_grid, 256, SM64>>>();
    // Layer 4
    row_gemm<64, 32, KSPLIT, true, 3, 2><<<NN / 64, 256>>>(nullptr, W4);
    convert_g<<<NN * 32 / 256, 256>>>(3);
    big_mma<32><<<big_grid, 256, SM32>>>();

    reduce_out<<<NN * 32 / 4 / 256, 256>>>(out);
}